// round 9
// baseline (speedup 1.0000x reference)
#include <cuda_runtime.h>
#include <math.h>
#include <stdint.h>

// ---------------- problem constants ----------------
#define TOKENS 2048
#define DM     2048
#define DS     128
#define NH     512
#define NTOT   16384
#define NCET   256
#define OUTW   20480
#define MAXK   32
#define SK0    4
#define SK1    2

// ---------------- device scratch ----------------
__device__ float  g_H[TOKENS * NH];
__device__ float  g_Hp[SK0 * TOKENS * NH];
__device__ float  g_csp[SK1 * TOKENS * 320];
__device__ float  g_W[DM * NH];
__device__ float  g_b[NH];
__device__ float4 g_wtau4[DM];
__device__ float  g_btau[4];
__device__ float  g_tau[TOKENS * 4];
__device__ float  g_embn[NTOT * DS];
__device__ float  g_ce[NCET * DS];
__device__ float  g_cebig[512 * 320];
__device__ float  g_csAll[TOKENS * 320];
__device__ float  g_csum[320];
__device__ float  g_nmass[OUTW];
__device__ int    g_cnt[320];
__device__ int    g_list[320 * 2048];
__device__ int    g_topc[TOKENS * 4 * 8];
__device__ float  g_scores[TOKENS * 4 * 512];
__device__ double g_aux;

// ---------------- f32x2 packed helpers ----------------
__device__ __forceinline__ unsigned long long pk2(float x) {
    unsigned long long r;
    asm("mov.b64 %0, {%1, %1};" : "=l"(r) : "f"(x));
    return r;
}
__device__ __forceinline__ void fma2(unsigned long long& c,
                                     unsigned long long a, unsigned long long b) {
    asm("fma.rn.f32x2 %0, %1, %2, %0;" : "+l"(c) : "l"(a), "l"(b));
}
__device__ __forceinline__ float2 upk(unsigned long long p) {
    float2 f;
    asm("mov.b64 {%0, %1}, %2;" : "=f"(f.x), "=f"(f.y) : "l"(p));
    return f;
}

// gate nonlinearity (matches reference float path)
__device__ __forceinline__ float fgate(float raw) {
    float gt = (raw > 0.f) ? raw : 1e-8f * expf(raw);
    return expf(gt) - 1.0f;
}

// tf32 hi/lo split for 3xTF32
__device__ __forceinline__ void cvt_hi_lo(float v, float& hi, float& lo) {
    unsigned hb, lb;
    asm("cvt.rna.tf32.f32 %0, %1;" : "=r"(hb) : "f"(v));
    hi = __uint_as_float(hb);
    float rest = v - hi;
    asm("cvt.rna.tf32.f32 %0, %1;" : "=r"(lb) : "f"(rest));
    lo = __uint_as_float(lb);
}

#define MMA_TF32(c, a, b)                                                    \
    asm volatile("mma.sync.aligned.m16n8k8.row.col.f32.tf32.tf32.f32 "       \
        "{%0,%1,%2,%3}, {%4,%5,%6,%7}, {%8,%9}, {%0,%1,%2,%3};"              \
        : "+f"((c)[0]), "+f"((c)[1]), "+f"((c)[2]), "+f"((c)[3])             \
        : "r"((a).x), "r"((a).y), "r"((a).z), "r"((a).w),                    \
          "r"((b).x), "r"((b).y))

// ---------------- normalize embeddings (warp per row) ----------------
__global__ void norm_kernel(const float* __restrict__ emb,
                            const float* __restrict__ cqk,
                            const float* __restrict__ cv,
                            const float* __restrict__ cknow) {
    int wid = threadIdx.x >> 5, lane = threadIdx.x & 31;
    int r = blockIdx.x * 8 + wid;
    const float* src;
    if (r < NTOT) {
        src = emb + (size_t)r * DS;
    } else {
        int c = r - NTOT;
        if (c < 64)       src = cqk + (size_t)c * DS;
        else if (c < 128) src = cv + (size_t)(c - 64) * DS;
        else              src = cknow + (size_t)(c - 128) * DS;
    }
    float4 v = ((const float4*)src)[lane];
    float ss = v.x * v.x + v.y * v.y + v.z * v.z + v.w * v.w;
    #pragma unroll
    for (int o = 16; o; o >>= 1) ss += __shfl_xor_sync(0xffffffffu, ss, o);
    float invn = 1.0f / (sqrtf(ss) + 1e-8f);
    float4 ov = make_float4(v.x * invn, v.y * invn, v.z * invn, v.w * invn);
    if (r < NTOT) ((float4*)(g_embn + (size_t)r * DS))[lane] = ov;
    else          ((float4*)(g_ce + (size_t)(r - NTOT) * DS))[lane] = ov;
}

// ---------------- pack weights ----------------
__global__ void pack_kernel(const float* __restrict__ Wa, const float* __restrict__ ba,
                            const float* __restrict__ Wk, const float* __restrict__ bk,
                            const float* __restrict__ Wta, const float* __restrict__ bta,
                            const float* __restrict__ Wtk, const float* __restrict__ btk) {
    int i = blockIdx.x * blockDim.x + threadIdx.x;
    if (i >= DM * NH) return;
    int k = i >> 9, c = i & 511;
    g_W[i] = (c < 384) ? Wa[(size_t)k * 384 + c] : Wk[(size_t)k * 128 + (c - 384)];
    if (k == 0) g_b[c] = (c < 384) ? ba[c] : bk[c - 384];
    if (i < DM)
        g_wtau4[i] = make_float4(Wta[i * 3 + 0], Wta[i * 3 + 1], Wta[i * 3 + 2], Wtk[i]);
    if (i == 0) {
        g_btau[0] = bta[0]; g_btau[1] = bta[1]; g_btau[2] = bta[2]; g_btau[3] = btk[0];
    }
}

// ---------------- cebig + accumulator zeroing ----------------
__global__ void cebig_kernel() {
    int i = blockIdx.x * blockDim.x + threadIdx.x;
    if (i < 320) { g_csum[i] = 0.f; g_cnt[i] = 0; }
    if (i < OUTW) g_nmass[i] = 0.f;
    if (i == 0) g_aux = 0.0;
    if (i >= 512 * 320) return;
    int k = i / 320, c = i - (i / 320) * 320;
    int ce_row, kb;
    if (c < 64)       { ce_row = c;             kb = 0;   }
    else if (c < 128) { ce_row = c - 64;        kb = 128; }
    else if (c < 192) { ce_row = c - 128 + 64;  kb = 256; }
    else              { ce_row = c - 192 + 128; kb = 384; }
    g_cebig[i] = (k >= kb && k < kb + 128) ? g_ce[ce_row * DS + (k - kb)] : 0.f;
}

// ---------------- zero the whole output tensor ----------------
__global__ void zerofill_kernel(float4* __restrict__ out4) {
    int i = blockIdx.x * blockDim.x + threadIdx.x;
    const int stride = 5120 * 256;
    float4 z = make_float4(0.f, 0.f, 0.f, 0.f);
    #pragma unroll
    for (int r = 0; r < 8; r++) out4[i + r * stride] = z;
}

// ---------------- tau ----------------
__global__ void tau_kernel(const float* __restrict__ x) {
    int wid = threadIdx.x >> 5, lane = threadIdx.x & 31;
    int token = blockIdx.x * 8 + wid;
    const float* xr = x + (size_t)token * DM;
    float a0 = 0.f, a1 = 0.f, a2 = 0.f, a3 = 0.f;
    #pragma unroll
    for (int q = 0; q < 16; q++) {
        int k0 = q * 128 + lane * 4;
        float4 xv = *(const float4*)(xr + k0);
        float4 w0 = g_wtau4[k0 + 0];
        float4 w1 = g_wtau4[k0 + 1];
        float4 w2 = g_wtau4[k0 + 2];
        float4 w3 = g_wtau4[k0 + 3];
        a0 = fmaf(xv.x, w0.x, fmaf(xv.y, w1.x, fmaf(xv.z, w2.x, fmaf(xv.w, w3.x, a0))));
        a1 = fmaf(xv.x, w0.y, fmaf(xv.y, w1.y, fmaf(xv.z, w2.y, fmaf(xv.w, w3.y, a1))));
        a2 = fmaf(xv.x, w0.z, fmaf(xv.y, w1.z, fmaf(xv.z, w2.z, fmaf(xv.w, w3.z, a2))));
        a3 = fmaf(xv.x, w0.w, fmaf(xv.y, w1.w, fmaf(xv.z, w2.w, fmaf(xv.w, w3.w, a3))));
    }
    #pragma unroll
    for (int o = 16; o; o >>= 1) {
        a0 += __shfl_xor_sync(0xffffffffu, a0, o);
        a1 += __shfl_xor_sync(0xffffffffu, a1, o);
        a2 += __shfl_xor_sync(0xffffffffu, a2, o);
        a3 += __shfl_xor_sync(0xffffffffu, a3, o);
    }
    if (lane == 0) {
        g_tau[token * 4 + 0] = a0 + g_btau[0];
        g_tau[token * 4 + 1] = a1 + g_btau[1];
        g_tau[token * 4 + 2] = a2 + g_btau[2];
        g_tau[token * 4 + 3] = a3 + g_btau[3];
    }
}

// ---------------- GEMM0: 3xTF32 mma.sync, BM=BN=128, BK=16, split-K --------
// smem frag-major layouts:
//   As[p(2)][mb(8)][h(2)][128]: lane*4 + j holds a_j for (mb, lane)
//   Bs[p(2)][nb(16)][h(2)][64]: lane*2 + j holds b_j for (nb, lane)
__global__ __launch_bounds__(256, 2) void sgemm0_kernel(const float* __restrict__ x) {
    __shared__ __align__(16) float As[4096];
    __shared__ __align__(16) float Bs[4096];

    int bm = blockIdx.x * 128, bn = blockIdx.y * 128;
    int kbeg = blockIdx.z * (DM / SK0);
    float* C = g_Hp + (size_t)blockIdx.z * TOKENS * NH;

    int tid = threadIdx.x;
    int lane = tid & 31, wid = tid >> 5;
    int wm = wid & 1, wn = wid >> 1;

    // A staging: thread -> (row, k-half)
    int srow = tid >> 1, sp = tid & 1;
    int smb = srow >> 4;
    int srl = srow & 7, srb = (srow >> 3) & 1;
    const float* Asrc = x + (size_t)(bm + srow) * DM + kbeg + sp * 8;

    // B staging: thread -> (k-row, n8-block)
    int skr = tid >> 4, snb = tid & 15;
    int sbp = skr >> 3, st7 = skr & 7;
    int sbt = st7 & 3, sbj = st7 >> 2;
    const float* Bsrc = g_W + (size_t)(kbeg + skr) * NH + bn + snb * 8;

    float acc[4][4][4];
    #pragma unroll
    for (int a = 0; a < 4; a++)
        #pragma unroll
        for (int b = 0; b < 4; b++)
            #pragma unroll
            for (int c = 0; c < 4; c++) acc[a][b][c] = 0.f;

    for (int kt = 0; kt < DM / SK0; kt += 16) {
        // ---- stage A (staggered scatter to break bank conflicts) ----
        {
            float4 v0 = *(const float4*)(Asrc + kt);
            float4 v1 = *(const float4*)(Asrc + kt + 4);
            float ae[8] = {v0.x, v0.y, v0.z, v0.w, v1.x, v1.y, v1.z, v1.w};
            int abase = (sp * 8 + smb) * 256;       // ((p*8+mb)*2)*128
            #pragma unroll
            for (int i = 0; i < 8; i++) {
                int kkk = (i + srow) & 7;
                float v = ae[kkk];
                int t = kkk & 3, j = ((kkk >> 2) << 1) | srb;
                int idx = abase + (((srl << 2) | t) << 2) + j;
                float hi, lo; cvt_hi_lo(v, hi, lo);
                As[idx] = hi; As[idx + 128] = lo;
            }
        }
        // ---- stage B ----
        {
            float4 v0 = *(const float4*)(Bsrc + (size_t)kt * NH);
            float4 v1 = *(const float4*)(Bsrc + (size_t)kt * NH + 4);
            float be[8] = {v0.x, v0.y, v0.z, v0.w, v1.x, v1.y, v1.z, v1.w};
            int bbase = (sbp * 16 + snb) * 128;     // ((p*16+nb)*2)*64
            #pragma unroll
            for (int i = 0; i < 8; i++) {
                int gg = (i + snb) & 7;
                float v = be[gg];
                int idx = bbase + (((gg << 2) | sbt) << 1) + sbj;
                float hi, lo; cvt_hi_lo(v, hi, lo);
                Bs[idx] = hi; Bs[idx + 64] = lo;
            }
        }
        __syncthreads();

        #pragma unroll
        for (int p = 0; p < 2; p++) {
            uint2 bh[4], bl[4];
            #pragma unroll
            for (int ni = 0; ni < 4; ni++) {
                int nb = wn * 4 + ni;
                const float* bp = &Bs[(p * 16 + nb) * 128 + lane * 2];
                bh[ni] = *(const uint2*)bp;
                bl[ni] = *(const uint2*)(bp + 64);
            }
            #pragma unroll
            for (int mi = 0; mi < 4; mi++) {
                int mb = wm * 4 + mi;
                const float* ap = &As[(p * 8 + mb) * 256 + lane * 4];
                uint4 ah = *(const uint4*)ap;
                uint4 al = *(const uint4*)(ap + 128);
                #pragma unroll
                for (int ni = 0; ni < 4; ni++) {
                    MMA_TF32(acc[mi][ni], al, bh[ni]);
                    MMA_TF32(acc[mi][ni], ah, bl[ni]);
                    MMA_TF32(acc[mi][ni], ah, bh[ni]);
                }
            }
        }
        __syncthreads();
    }

    // epilogue: c0,c1 -> (g, 2t..2t+1); c2,c3 -> (g+8, ...)
    int g = lane >> 2, t = lane & 3;
    #pragma unroll
    for (int mi = 0; mi < 4; mi++) {
        int row0 = bm + (wm * 4 + mi) * 16 + g;
        #pragma unroll
        for (int ni = 0; ni < 4; ni++) {
            int col = bn + (wn * 4 + ni) * 8 + t * 2;
            *(float2*)&C[(size_t)row0 * NH + col] =
                make_float2(acc[mi][ni][0], acc[mi][ni][1]);
            *(float2*)&C[(size_t)(row0 + 8) * NH + col] =
                make_float2(acc[mi][ni][2], acc[mi][ni][3]);
        }
    }
}

// ---------------- GEMM1: csp[z] = H @ cebig (split-K, 8x4, FFMA2) ----------
#define APAD 4
#define LDAS (128 + APAD)
__global__ __launch_bounds__(256) void sgemm1_kernel() {
    constexpr int Kc = 512 / SK1;
    const float* A = g_H;
    const float* B = g_cebig;
    float* C = g_csp + (size_t)blockIdx.z * TOKENS * 320;
    int kbeg = blockIdx.z * Kc;

    __shared__ __align__(16) float As[16 * LDAS];
    __shared__ __align__(16) float Bs[16 * 64];

    int bm = blockIdx.x * 128, bn = blockIdx.y * 64;
    int tid = threadIdx.x;

    int am0 = tid >> 2,        ak0 = (tid & 3) << 2;
    int am1 = (tid + 256) >> 2, ak1 = ((tid + 256) & 3) << 2;
    int bk = tid >> 4, bn0 = (tid & 15) << 2;

    const float* Ap0 = A + (size_t)(bm + am0) * NH + kbeg + ak0;
    const float* Ap1 = A + (size_t)(bm + am1) * NH + kbeg + ak1;
    const float* Bp  = B + (size_t)(kbeg + bk) * 320 + bn + bn0;

    unsigned long long acc[4][4];
    #pragma unroll
    for (int i = 0; i < 4; i++)
        #pragma unroll
        for (int j = 0; j < 4; j++) acc[i][j] = 0ULL;

    int ty = tid >> 4, tx = tid & 15;
    int m0 = ty * 8, n0 = tx * 4;

    float4 pa0 = *(const float4*)Ap0;
    float4 pa1 = *(const float4*)Ap1;
    float4 pb  = *(const float4*)Bp;

    for (int kt = 0; kt < Kc; kt += 16) {
        As[(ak0 + 0) * LDAS + am0] = pa0.x;
        As[(ak0 + 1) * LDAS + am0] = pa0.y;
        As[(ak0 + 2) * LDAS + am0] = pa0.z;
        As[(ak0 + 3) * LDAS + am0] = pa0.w;
        As[(ak1 + 0) * LDAS + am1] = pa1.x;
        As[(ak1 + 1) * LDAS + am1] = pa1.y;
        As[(ak1 + 2) * LDAS + am1] = pa1.z;
        As[(ak1 + 3) * LDAS + am1] = pa1.w;
        *(float4*)&Bs[bk * 64 + bn0] = pb;
        __syncthreads();

        if (kt + 16 < Kc) {
            pa0 = *(const float4*)(Ap0 + kt + 16);
            pa1 = *(const float4*)(Ap1 + kt + 16);
            pb  = *(const float4*)(Bp + (size_t)(kt + 16) * 320);
        }

        #pragma unroll
        for (int kk = 0; kk < 16; kk++) {
            ulonglong2 a01 = *(const ulonglong2*)&As[kk * LDAS + m0];
            ulonglong2 a23 = *(const ulonglong2*)&As[kk * LDAS + m0 + 4];
            float4 b = *(const float4*)&Bs[kk * 64 + n0];
            unsigned long long bp0 = pk2(b.x), bp1 = pk2(b.y);
            unsigned long long bp2 = pk2(b.z), bp3 = pk2(b.w);
            fma2(acc[0][0], a01.x, bp0); fma2(acc[0][1], a01.x, bp1);
            fma2(acc[0][2], a01.x, bp2); fma2(acc[0][3], a01.x, bp3);
            fma2(acc[1][0], a01.y, bp0); fma2(acc[1][1], a01.y, bp1);
            fma2(acc[1][2], a01.y, bp2); fma2(acc[1][3], a01.y, bp3);
            fma2(acc[2][0], a23.x, bp0); fma2(acc[2][1], a23.x, bp1);
            fma2(acc[2][2], a23.x, bp2); fma2(acc[2][3], a23.x, bp3);
            fma2(acc[3][0], a23.y, bp0); fma2(acc[3][1], a23.y, bp1);
            fma2(acc[3][2], a23.y, bp2); fma2(acc[3][3], a23.y, bp3);
        }
        __syncthreads();
    }

    #pragma unroll
    for (int mp = 0; mp < 4; mp++) {
        int row = bm + m0 + mp * 2;
        #pragma unroll
        for (int j = 0; j < 4; j++) {
            float2 v = upk(acc[mp][j]);
            int col = bn + n0 + j;
            C[(size_t)row * 320 + col] = v.x;
            C[(size_t)(row + 1) * 320 + col] = v.y;
        }
    }
}

// ---------------- reduce split-K partials ----------------
__global__ void reduceH_kernel() {
    int i = blockIdx.x * blockDim.x + threadIdx.x;
    const float4* p = (const float4*)g_Hp;
    constexpr int Q = TOKENS * NH / 4;
    float4 s = p[i];
    #pragma unroll
    for (int z = 1; z < SK0; z++) {
        float4 t = p[i + z * Q];
        s.x += t.x; s.y += t.y; s.z += t.z; s.w += t.w;
    }
    float4 b = ((const float4*)g_b)[i & 127];
    s.x += b.x; s.y += b.y; s.z += b.z; s.w += b.w;
    ((float4*)g_H)[i] = s;
}

__global__ void reduceCS_kernel() {
    int i = blockIdx.x * blockDim.x + threadIdx.x;
    const float4* p = (const float4*)g_csp;
    constexpr int Q = TOKENS * 320 / 4;
    float4 s = p[i];
    float4 t = p[i + Q];
    s.x += t.x; s.y += t.y; s.z += t.z; s.w += t.w;
    ((float4*)g_csAll)[i] = s;
}

// ---------------- cluster softmax + top-8 + list build ----------------
__global__ void cluster_kernel() {
    int wid = threadIdx.x >> 5, lane = threadIdx.x & 31;
    int pair = blockIdx.x * 8 + wid;
    int token = pair >> 2, g = pair & 3;

    int nc   = (g == 3) ? 128 : 64;
    int base = (g < 3) ? g * 64 : 192;
    const float* cs = g_csAll + (size_t)token * 320 + base;

    float v[4];
    #pragma unroll
    for (int j = 0; j < 4; j++) {
        int c = j * 32 + lane;
        v[j] = (c < nc) ? cs[c] : -INFINITY;
    }

    float m = fmaxf(fmaxf(v[0], v[1]), fmaxf(v[2], v[3]));
    #pragma unroll
    for (int o = 16; o; o >>= 1) m = fmaxf(m, __shfl_xor_sync(0xffffffffu, m, o));
    float ssum = 0.f;
    #pragma unroll
    for (int j = 0; j < 4; j++) ssum += expf(v[j] - m);
    #pragma unroll
    for (int o = 16; o; o >>= 1) ssum += __shfl_xor_sync(0xffffffffu, ssum, o);

    #pragma unroll
    for (int j = 0; j < 4; j++) {
        int c = j * 32 + lane;
        if (c < nc) atomicAdd(&g_csum[base + c], expf(v[j] - m) / ssum);
    }

    unsigned rm = 0;
    int mytop = 0;
    for (int it = 0; it < 8; it++) {
        unsigned long long best = 0ULL;
        #pragma unroll
        for (int j = 0; j < 4; j++) {
            if (!((rm >> j) & 1u)) {
                int c = j * 32 + lane;
                unsigned b = __float_as_uint(v[j]);
                unsigned u = (b & 0x80000000u) ? ~b : (b | 0x80000000u);
                unsigned long long k = (((unsigned long long)u) << 32) | (unsigned)(256 - c);
                if (k > best) best = k;
            }
        }
        #pragma unroll
        for (int o = 16; o; o >>= 1) {
            unsigned long long t2 = __shfl_xor_sync(0xffffffffu, best, o);
            if (t2 > best) best = t2;
        }
        int idx = 256 - (int)(best & 0xffffffffu);
        if (it == lane) mytop = idx;
        if ((idx & 31) == lane) rm |= 1u << (idx >> 5);
    }

    if (lane < 8) {
        g_topc[(size_t)pair * 8 + lane] = mytop;
        int pos = atomicAdd(&g_cnt[base + mytop], 1);
        g_list[(size_t)(base + mytop) * 2048 + pos] = token | (lane << 16);
    }
}

// ---------------- cluster-grouped score GEMM ----------------
__global__ void score_kernel() {
    __shared__ __align__(16) float As[64 * 64];
    __shared__ __align__(16) float Bs[64 * 64];
    __shared__ int s_tok[64];
    __shared__ int s_slot[64];

    int gc = blockIdx.x;
    int cnt = g_cnt[gc];
    int start = blockIdx.y * 64;
    if (start >= cnt) return;

    int g  = (gc < 64) ? 0 : (gc < 128) ? 1 : (gc < 192) ? 2 : 3;
    int cl = gc - ((g < 3) ? g * 64 : 192);
    int embbase = (g < 2) ? 0 : ((g == 2) ? 4096 : 8192);
    int nbase = embbase + cl * 64;

    int t = threadIdx.x;
    if (t < 64) {
        if (start + t < cnt) {
            int e = g_list[(size_t)gc * 2048 + start + t];
            s_tok[t] = e & 0xffff;
            s_slot[t] = e >> 16;
        } else {
            s_tok[t] = -1; s_slot[t] = 0;
        }
    }
    __syncthreads();

    int m = t & 63, c4 = t >> 6;
    int ty = t >> 4, tx = t & 15;

    unsigned long long acc[4][2];
    #pragma unroll
    for (int i = 0; i < 4; i++) { acc[i][0] = 0ULL; acc[i][1] = 0ULL; }

    int tok = s_tok[m];
    const float* hrow = (tok >= 0) ? (g_H + (size_t)tok * NH + g * 128) : g_embn;
    const float* erow = g_embn + (size_t)(nbase + m) * DS;

    for (int half = 0; half < 2; half++) {
        int kb = half * 64;
        #pragma unroll
        for (int i = 0; i < 4; i++) {
            int k0 = c4 * 4 + i * 16;
            float4 ve = *(const float4*)(erow + kb + k0);
            Bs[(k0 + 0) * 64 + m] = ve.x;
            Bs[(k0 + 1) * 64 + m] = ve.y;
            Bs[(k0 + 2) * 64 + m] = ve.z;
            Bs[(k0 + 3) * 64 + m] = ve.w;
            float4 vh = *(const float4*)(hrow + kb + k0);
            As[(k0 + 0) * 64 + m] = vh.x;
            As[(k0 + 1) * 64 + m] = vh.y;
            As[(k0 + 2) * 64 + m] = vh.z;
            As[(k0 + 3) * 64 + m] = vh.w;
        }
        __syncthreads();

        #pragma unroll 4
        for (int k = 0; k < 64; k++) {
            float a[4];
            *(float4*)a = *(const float4*)&As[k * 64 + ty * 4];
            ulonglong2 bb = *(const ulonglong2*)&Bs[k * 64 + tx * 4];
            #pragma unroll
            for (int i = 0; i < 4; i++) {
                unsigned long long ap = pk2(a[i]);
                fma2(acc[i][0], ap, bb.x);
                fma2(acc[i][1], ap, bb.y);
            }
        }
        __syncthreads();
    }

    #pragma unroll
    for (int i = 0; i < 4; i++) {
        int mm = ty * 4 + i;
        int tok2 = s_tok[mm];
        if (tok2 >= 0) {
            float2 p0 = upk(acc[i][0]);
            float2 p1 = upk(acc[i][1]);
            float4 v = make_float4(p0.x, p0.y, p1.x, p1.y);
            *(float4*)(g_scores + ((size_t)tok2 * 4 + g) * 512 + s_slot[mm] * 64 + tx * 4) = v;
        }
    }
}

// ---------------- gate + sparse output write (warp per pair) ----------------
__global__ void gate_out_kernel(float* __restrict__ out) {
    int wid = threadIdx.x >> 5, lane = threadIdx.x & 31;
    int pair = blockIdx.x * 8 + wid;
    int token = pair >> 2, g = pair & 3;
    int outbase = g * 4096;

    const float* srow = g_scores + (size_t)pair * 512;
    float tau = g_tau[pair];
    int tcl = (lane < 8) ? g_topc[(size_t)pair * 8 + lane] : 0;

    float raw[16];
    unsigned u[16];
    unsigned lmax = 0;
    #pragma unroll
    for (int i = 0; i < 16; i++) {
        raw[i] = srow[i * 32 + lane] - tau;
        unsigned b = __float_as_uint(raw[i]);
        u[i] = (b & 0x80000000u) ? ~b : (b | 0x80000000u);
        lmax = (u[i] > lmax) ? u[i] : lmax;
    }
    unsigned umax = __reduce_max_sync(0xffffffffu, lmax);

    unsigned lo = 0, hi = umax;
    while (lo < hi) {
        unsigned mid = lo + ((hi - lo + 1) >> 1);
        int c = 0;
        #pragma unroll
        for (int i = 0; i < 16; i++) c += (u[i] >= mid);
        if (__reduce_add_sync(0xffffffffu, (unsigned)c) >= MAXK) lo = mid;
        else hi = mid - 1;
    }
    unsigned tb = (lo & 0x80000000u) ? (lo ^ 0x80000000u) : ~lo;
    unsigned mb = (umax & 0x80000000u) ? (umax ^ 0x80000000u) : ~umax;
    float raw_thr = __uint_as_float(tb);
    float eg_thr = fgate(raw_thr);
    float eg_max = fgate(__uint_as_float(mb));

    bool full = (eg_thr <= 4e-7f);
    float cand_lo = full ? -INFINITY : (raw_thr - 2.5e-7f);

    float eg[16];
    float s = 0.f;
    #pragma unroll
    for (int i = 0; i < 16; i++) {
        float e = -1.f;
        if (raw[i] >= cand_lo) {
            float ev = fgate(raw[i]);
            if (ev >= eg_thr) { e = ev; s += ev; }
        }
        eg[i] = e;
    }
    #pragma unroll
    for (int o = 16; o; o >>= 1) s += __shfl_xor_sync(0xffffffffu, s, o);
    float r = tanhf(eg_max) / (s + 1e-8f);

    float* orow = out + (size_t)token * OUTW + outbase;
    #pragma unroll
    for (int i = 0; i < 16; i++) {
        int tc = __shfl_sync(0xffffffffu, tcl, i >> 1);
        if (eg[i] > 0.f) {
            float val = eg[i] * r;
            if (val > 0.f) {
                int col = tc * 64 + (i & 1) * 32 + lane;
                orow[col] = val;
                atomicAdd(&g_nmass[outbase + col], val);
            }
        }
    }
}

// ---------------- aux: parallel partial + write ----------------
__global__ void aux_partial_kernel() {
    int i = blockIdx.x * blockDim.x + threadIdx.x;
    int lane = threadIdx.x & 31, wid = threadIdx.x >> 5;
    double acc = 0.0;
    if (i < 320 + OUTW) {
        if (i < 320) {
            int nc = (i < 192) ? 64 : 128;
            double fr = (double)g_csum[i] / 2048.0;
            double d = fr - 1.0 / nc;
            acc = d * d * nc;
        } else {
            int j = i - 320;
            int N = (j < 12288) ? 4096 : 8192;
            double fr = (double)g_nmass[j] / 2048.0;
            double d = fr - 1.0 / N;
            acc = d * d * N;
        }
    }
    #pragma unroll
    for (int o = 16; o; o >>= 1) acc += __shfl_xor_sync(0xffffffffu, acc, o);
    __shared__ double rd[8];
    if (lane == 0) rd[wid] = acc;
    __syncthreads();
    if (threadIdx.x == 0) {
        double t = rd[0] + rd[1] + rd[2] + rd[3] + rd[4] + rd[5] + rd[6] + rd[7];
        atomicAdd(&g_aux, t);
    }
}

__global__ void aux_write_kernel(float* __restrict__ out, long long outsize) {
    out[outsize - 1] = (float)g_aux;
}

// ---------------- launch ----------------
extern "C" void kernel_launch(void* const* d_in, const int* in_sizes, int n_in,
                              void* d_out, int out_size) {
    const float* x    = (const float*)d_in[0];
    const float* emb  = (const float*)d_in[1];
    const float* Wa   = (const float*)d_in[2];
    const float* ba   = (const float*)d_in[3];
    const float* Wk   = (const float*)d_in[4];
    const float* bk   = (const float*)d_in[5];
    const float* Wta  = (const float*)d_in[6];
    const float* bta  = (const float*)d_in[7];
    const float* Wtk  = (const float*)d_in[8];
    const float* btk  = (const float*)d_in[9];
    const float* cqk  = (const float*)d_in[10];
    const float* cv   = (const float*)d_in[11];
    const float* cknw = (const float*)d_in[12];
    float* out = (float*)d_out;

    pack_kernel<<<(DM * NH + 255) / 256, 256>>>(Wa, ba, Wk, bk, Wta, bta, Wtk, btk);
    norm_kernel<<<(NTOT + NCET) / 8, 256>>>(emb, cqk, cv, cknw);
    cebig_kernel<<<(512 * 320 + 255) / 256, 256>>>();
    sgemm0_kernel<<<dim3(16, 4, SK0), 256>>>(x);        // 4th launch -> profiled
    zerofill_kernel<<<5120, 256>>>((float4*)out);
    reduceH_kernel<<<TOKENS * NH / 4 / 256, 256>>>();
    tau_kernel<<<TOKENS / 8, 256>>>(x);
    sgemm1_kernel<<<dim3(16, 5, SK1), 256>>>();
    reduceCS_kernel<<<TOKENS * 320 / 4 / 256, 256>>>();
    cluster_kernel<<<TOKENS * 4 / 8, 256>>>();
    score_kernel<<<dim3(320, 32), 256>>>();
    gate_out_kernel<<<TOKENS * 4 / 8, 256>>>(out);
    aux_partial_kernel<<<(320 + OUTW + 255) / 256, 256>>>();
    aux_write_kernel<<<1, 1>>>(out, (long long)out_size);
}

// round 12
// speedup vs baseline: 1.0625x; 1.0625x over previous
#include <cuda_runtime.h>
#include <math.h>
#include <stdint.h>

// ---------------- problem constants ----------------
#define TOKENS 2048
#define DM     2048
#define DS     128
#define NH     512
#define NTOT   16384
#define NCET   256
#define OUTW   20480
#define MAXK   32
#define SK0    4
#define SK1    2

// ---------------- device scratch ----------------
__device__ float  g_H[TOKENS * NH];
__device__ float  g_Hp[SK0 * TOKENS * NH];
__device__ float  g_csp[SK1 * TOKENS * 320];
__device__ float  g_b[NH];
__device__ float4 g_wtau4[DM];
__device__ float  g_btau[4];
__device__ float  g_tau[TOKENS * 4];
__device__ float  g_embn[NTOT * DS];
__device__ float  g_ce[NCET * DS];
__device__ float  g_cebig[512 * 320];
__device__ float  g_csum[320];
__device__ float  g_nmass[OUTW];
__device__ int    g_cnt[320];
__device__ int    g_list[320 * 2048];
__device__ int    g_topc[TOKENS * 4 * 8];
__device__ float  g_scores[TOKENS * 4 * 512];
__device__ double g_aux;

// ---------------- f32x2 packed helpers ----------------
__device__ __forceinline__ unsigned long long pk2(float x) {
    unsigned long long r;
    asm("mov.b64 %0, {%1, %1};" : "=l"(r) : "f"(x));
    return r;
}
__device__ __forceinline__ void fma2(unsigned long long& c,
                                     unsigned long long a, unsigned long long b) {
    asm("fma.rn.f32x2 %0, %1, %2, %0;" : "+l"(c) : "l"(a), "l"(b));
}
__device__ __forceinline__ float2 upk(unsigned long long p) {
    float2 f;
    asm("mov.b64 {%0, %1}, %2;" : "=f"(f.x), "=f"(f.y) : "l"(p));
    return f;
}

// gate nonlinearity (matches reference float path)
__device__ __forceinline__ float fgate(float raw) {
    float gt = (raw > 0.f) ? raw : 1e-8f * expf(raw);
    return expf(gt) - 1.0f;
}

// ---------------- normalize embeddings (warp per row) ----------------
__global__ void norm_kernel(const float* __restrict__ emb,
                            const float* __restrict__ cqk,
                            const float* __restrict__ cv,
                            const float* __restrict__ cknow) {
    int wid = threadIdx.x >> 5, lane = threadIdx.x & 31;
    int r = blockIdx.x * 8 + wid;
    const float* src;
    if (r < NTOT) {
        src = emb + (size_t)r * DS;
    } else {
        int c = r - NTOT;
        if (c < 64)       src = cqk + (size_t)c * DS;
        else if (c < 128) src = cv + (size_t)(c - 64) * DS;
        else              src = cknow + (size_t)(c - 128) * DS;
    }
    float4 v = ((const float4*)src)[lane];
    float ss = v.x * v.x + v.y * v.y + v.z * v.z + v.w * v.w;
    #pragma unroll
    for (int o = 16; o; o >>= 1) ss += __shfl_xor_sync(0xffffffffu, ss, o);
    float invn = 1.0f / (sqrtf(ss) + 1e-8f);
    float4 ov = make_float4(v.x * invn, v.y * invn, v.z * invn, v.w * invn);
    if (r < NTOT) ((float4*)(g_embn + (size_t)r * DS))[lane] = ov;
    else          ((float4*)(g_ce + (size_t)(r - NTOT) * DS))[lane] = ov;
}

// ---------------- cebig + tau/bias pack + accumulator zeroing ----------------
__global__ void cebig_kernel(const float* __restrict__ ba, const float* __restrict__ bk,
                             const float* __restrict__ Wta, const float* __restrict__ bta,
                             const float* __restrict__ Wtk, const float* __restrict__ btk) {
    int i = blockIdx.x * blockDim.x + threadIdx.x;
    if (i < 320) { g_csum[i] = 0.f; g_cnt[i] = 0; }
    if (i < OUTW) g_nmass[i] = 0.f;
    if (i < NH) g_b[i] = (i < 384) ? ba[i] : bk[i - 384];
    if (i < DM)
        g_wtau4[i] = make_float4(Wta[i * 3 + 0], Wta[i * 3 + 1], Wta[i * 3 + 2], Wtk[i]);
    if (i == 0) {
        g_btau[0] = bta[0]; g_btau[1] = bta[1]; g_btau[2] = bta[2]; g_btau[3] = btk[0];
        g_aux = 0.0;
    }
    if (i >= 512 * 320) return;
    int k = i / 320, c = i - (i / 320) * 320;
    int ce_row, kb;
    if (c < 64)       { ce_row = c;             kb = 0;   }
    else if (c < 128) { ce_row = c - 64;        kb = 128; }
    else if (c < 192) { ce_row = c - 128 + 64;  kb = 256; }
    else              { ce_row = c - 192 + 128; kb = 384; }
    g_cebig[i] = (k >= kb && k < kb + 128) ? g_ce[ce_row * DS + (k - kb)] : 0.f;
}

// ---------------- zero the whole output tensor ----------------
__global__ void zerofill_kernel(float4* __restrict__ out4) {
    int i = blockIdx.x * blockDim.x + threadIdx.x;
    const int stride = 5120 * 256;
    float4 z = make_float4(0.f, 0.f, 0.f, 0.f);
    #pragma unroll
    for (int r = 0; r < 8; r++) out4[i + r * stride] = z;
}

// ---------------- tau ----------------
__global__ void tau_kernel(const float* __restrict__ x) {
    int wid = threadIdx.x >> 5, lane = threadIdx.x & 31;
    int token = blockIdx.x * 8 + wid;
    const float* xr = x + (size_t)token * DM;
    float a0 = 0.f, a1 = 0.f, a2 = 0.f, a3 = 0.f;
    #pragma unroll
    for (int q = 0; q < 16; q++) {
        int k0 = q * 128 + lane * 4;
        float4 xv = *(const float4*)(xr + k0);
        float4 w0 = g_wtau4[k0 + 0];
        float4 w1 = g_wtau4[k0 + 1];
        float4 w2 = g_wtau4[k0 + 2];
        float4 w3 = g_wtau4[k0 + 3];
        a0 = fmaf(xv.x, w0.x, fmaf(xv.y, w1.x, fmaf(xv.z, w2.x, fmaf(xv.w, w3.x, a0))));
        a1 = fmaf(xv.x, w0.y, fmaf(xv.y, w1.y, fmaf(xv.z, w2.y, fmaf(xv.w, w3.y, a1))));
        a2 = fmaf(xv.x, w0.z, fmaf(xv.y, w1.z, fmaf(xv.z, w2.z, fmaf(xv.w, w3.z, a2))));
        a3 = fmaf(xv.x, w0.w, fmaf(xv.y, w1.w, fmaf(xv.z, w2.w, fmaf(xv.w, w3.w, a3))));
    }
    #pragma unroll
    for (int o = 16; o; o >>= 1) {
        a0 += __shfl_xor_sync(0xffffffffu, a0, o);
        a1 += __shfl_xor_sync(0xffffffffu, a1, o);
        a2 += __shfl_xor_sync(0xffffffffu, a2, o);
        a3 += __shfl_xor_sync(0xffffffffu, a3, o);
    }
    if (lane == 0) {
        g_tau[token * 4 + 0] = a0 + g_btau[0];
        g_tau[token * 4 + 1] = a1 + g_btau[1];
        g_tau[token * 4 + 2] = a2 + g_btau[2];
        g_tau[token * 4 + 3] = a3 + g_btau[3];
    }
}

// ---------------- GEMM0: double-buffered 8x8 FFMA2, direct Wa/Wk reads ------
#define LDT 132

#define G0_LOAD(KOFF)                                            \
    pa0 = *(const float4*)(Ap + (KOFF));                         \
    pa1 = *(const float4*)(Ap + (KOFF) + 4);                     \
    pb0 = *(const float4*)(Bp + (size_t)(KOFF) * ldb);           \
    pb1 = *(const float4*)(Bp + (size_t)(KOFF) * ldb + 4);

#define G0_STORE(AS, BS)                                         \
    AS[(ak + 0) * LDT + am] = pa0.x;                             \
    AS[(ak + 1) * LDT + am] = pa0.y;                             \
    AS[(ak + 2) * LDT + am] = pa0.z;                             \
    AS[(ak + 3) * LDT + am] = pa0.w;                             \
    AS[(ak + 4) * LDT + am] = pa1.x;                             \
    AS[(ak + 5) * LDT + am] = pa1.y;                             \
    AS[(ak + 6) * LDT + am] = pa1.z;                             \
    AS[(ak + 7) * LDT + am] = pa1.w;                             \
    *(float4*)&BS[bkr * LDT + bn0] = pb0;                        \
    *(float4*)&BS[bkr * LDT + bn0 + 4] = pb1;

#define G0_COMPUTE(AS, BS)                                       \
    _Pragma("unroll")                                            \
    for (int kk = 0; kk < 16; kk++) {                            \
        ulonglong2 a01 = *(const ulonglong2*)&AS[kk * LDT + ty * 4];       \
        ulonglong2 a23 = *(const ulonglong2*)&AS[kk * LDT + 64 + ty * 4];  \
        float4 b0 = *(const float4*)&BS[kk * LDT + tx * 4];                \
        float4 b1 = *(const float4*)&BS[kk * LDT + 64 + tx * 4];           \
        unsigned long long bp[8];                                          \
        bp[0] = pk2(b0.x); bp[1] = pk2(b0.y); bp[2] = pk2(b0.z); bp[3] = pk2(b0.w); \
        bp[4] = pk2(b1.x); bp[5] = pk2(b1.y); bp[6] = pk2(b1.z); bp[7] = pk2(b1.w); \
        _Pragma("unroll")                                        \
        for (int j = 0; j < 8; j++) {                            \
            fma2(acc[0][j], a01.x, bp[j]);                       \
            fma2(acc[1][j], a01.y, bp[j]);                       \
            fma2(acc[2][j], a23.x, bp[j]);                       \
            fma2(acc[3][j], a23.y, bp[j]);                       \
        }                                                        \
    }

__global__ __launch_bounds__(256, 2) void sgemm0_kernel(const float* __restrict__ x,
                                                        const float* __restrict__ Wa,
                                                        const float* __restrict__ Wk) {
    __shared__ __align__(16) float As0[16 * LDT];
    __shared__ __align__(16) float Bs0[16 * LDT];
    __shared__ __align__(16) float As1[16 * LDT];
    __shared__ __align__(16) float Bs1[16 * LDT];

    int bm = blockIdx.x * 128;
    int bn_c = blockIdx.y * 128;                 // H column base
    int kbeg = blockIdx.z * (DM / SK0);
    float* C = g_Hp + (size_t)blockIdx.z * TOKENS * NH;

    int tid = threadIdx.x;
    int am = tid >> 1, ak = (tid & 1) << 3;
    int bkr = tid >> 4, bn0 = (tid & 15) << 3;
    int ty = tid >> 4, tx = tid & 15;

    const float* Ap = x + (size_t)(bm + am) * DM + kbeg + ak;
    const float* Bp; int ldb;
    if (blockIdx.y < 3) { Bp = Wa + (size_t)(kbeg + bkr) * 384 + bn_c + bn0; ldb = 384; }
    else                { Bp = Wk + (size_t)(kbeg + bkr) * 128 + bn0;        ldb = 128; }

    unsigned long long acc[4][8];
    #pragma unroll
    for (int i = 0; i < 4; i++)
        #pragma unroll
        for (int j = 0; j < 8; j++) acc[i][j] = 0ULL;

    float4 pa0, pa1, pb0, pb1;
    G0_LOAD(0);
    G0_STORE(As0, Bs0);
    __syncthreads();

    for (int kt = 0; kt < DM / SK0; kt += 32) {
        G0_LOAD(kt + 16);
        G0_COMPUTE(As0, Bs0);
        G0_STORE(As1, Bs1);
        __syncthreads();

        if (kt + 32 < DM / SK0) { G0_LOAD(kt + 32); }
        G0_COMPUTE(As1, Bs1);
        if (kt + 32 < DM / SK0) { G0_STORE(As0, Bs0); }
        __syncthreads();
    }

    #pragma unroll
    for (int mi = 0; mi < 4; mi++) {
        int row = bm + ((mi < 2) ? (ty * 4 + mi * 2) : (64 + ty * 4 + (mi - 2) * 2));
        #pragma unroll
        for (int j = 0; j < 8; j++) {
            int col = bn_c + ((j < 4) ? (tx * 4 + j) : (64 + tx * 4 + (j - 4)));
            float2 v = upk(acc[mi][j]);
            C[(size_t)row * NH + col] = v.x;
            C[(size_t)(row + 1) * NH + col] = v.y;
        }
    }
}

// ---------------- GEMM1: csp[z] = H @ cebig (split-K, 8x4, FFMA2) ----------
#define APAD 4
#define LDAS (128 + APAD)
__global__ __launch_bounds__(256) void sgemm1_kernel() {
    constexpr int Kc = 512 / SK1;
    const float* A = g_H;
    const float* B = g_cebig;
    float* C = g_csp + (size_t)blockIdx.z * TOKENS * 320;
    int kbeg = blockIdx.z * Kc;

    __shared__ __align__(16) float As[16 * LDAS];
    __shared__ __align__(16) float Bs[16 * 64];

    int bm = blockIdx.x * 128, bn = blockIdx.y * 64;
    int tid = threadIdx.x;

    int am0 = tid >> 2,        ak0 = (tid & 3) << 2;
    int am1 = (tid + 256) >> 2, ak1 = ((tid + 256) & 3) << 2;
    int bk = tid >> 4, bn0 = (tid & 15) << 2;

    const float* Ap0 = A + (size_t)(bm + am0) * NH + kbeg + ak0;
    const float* Ap1 = A + (size_t)(bm + am1) * NH + kbeg + ak1;
    const float* Bp  = B + (size_t)(kbeg + bk) * 320 + bn + bn0;

    unsigned long long acc[4][4];
    #pragma unroll
    for (int i = 0; i < 4; i++)
        #pragma unroll
        for (int j = 0; j < 4; j++) acc[i][j] = 0ULL;

    int ty = tid >> 4, tx = tid & 15;
    int m0 = ty * 8, n0 = tx * 4;

    float4 pa0 = *(const float4*)Ap0;
    float4 pa1 = *(const float4*)Ap1;
    float4 pb  = *(const float4*)Bp;

    for (int kt = 0; kt < Kc; kt += 16) {
        As[(ak0 + 0) * LDAS + am0] = pa0.x;
        As[(ak0 + 1) * LDAS + am0] = pa0.y;
        As[(ak0 + 2) * LDAS + am0] = pa0.z;
        As[(ak0 + 3) * LDAS + am0] = pa0.w;
        As[(ak1 + 0) * LDAS + am1] = pa1.x;
        As[(ak1 + 1) * LDAS + am1] = pa1.y;
        As[(ak1 + 2) * LDAS + am1] = pa1.z;
        As[(ak1 + 3) * LDAS + am1] = pa1.w;
        *(float4*)&Bs[bk * 64 + bn0] = pb;
        __syncthreads();

        if (kt + 16 < Kc) {
            pa0 = *(const float4*)(Ap0 + kt + 16);
            pa1 = *(const float4*)(Ap1 + kt + 16);
            pb  = *(const float4*)(Bp + (size_t)(kt + 16) * 320);
        }

        #pragma unroll
        for (int kk = 0; kk < 16; kk++) {
            ulonglong2 a01 = *(const ulonglong2*)&As[kk * LDAS + m0];
            ulonglong2 a23 = *(const ulonglong2*)&As[kk * LDAS + m0 + 4];
            float4 b = *(const float4*)&Bs[kk * 64 + n0];
            unsigned long long bp0 = pk2(b.x), bp1 = pk2(b.y);
            unsigned long long bp2 = pk2(b.z), bp3 = pk2(b.w);
            fma2(acc[0][0], a01.x, bp0); fma2(acc[0][1], a01.x, bp1);
            fma2(acc[0][2], a01.x, bp2); fma2(acc[0][3], a01.x, bp3);
            fma2(acc[1][0], a01.y, bp0); fma2(acc[1][1], a01.y, bp1);
            fma2(acc[1][2], a01.y, bp2); fma2(acc[1][3], a01.y, bp3);
            fma2(acc[2][0], a23.x, bp0); fma2(acc[2][1], a23.x, bp1);
            fma2(acc[2][2], a23.x, bp2); fma2(acc[2][3], a23.x, bp3);
            fma2(acc[3][0], a23.y, bp0); fma2(acc[3][1], a23.y, bp1);
            fma2(acc[3][2], a23.y, bp2); fma2(acc[3][3], a23.y, bp3);
        }
        __syncthreads();
    }

    #pragma unroll
    for (int mp = 0; mp < 4; mp++) {
        int row = bm + m0 + mp * 2;
        #pragma unroll
        for (int j = 0; j < 4; j++) {
            float2 v = upk(acc[mp][j]);
            int col = bn + n0 + j;
            C[(size_t)row * 320 + col] = v.x;
            C[(size_t)(row + 1) * 320 + col] = v.y;
        }
    }
}

// ---------------- reduce split-K partials for H (adds bias) ----------------
__global__ void reduceH_kernel() {
    int i = blockIdx.x * blockDim.x + threadIdx.x;
    const float4* p = (const float4*)g_Hp;
    constexpr int Q = TOKENS * NH / 4;
    float4 s = p[i];
    #pragma unroll
    for (int z = 1; z < SK0; z++) {
        float4 t = p[i + z * Q];
        s.x += t.x; s.y += t.y; s.z += t.z; s.w += t.w;
    }
    float4 b = ((const float4*)g_b)[i & 127];
    s.x += b.x; s.y += b.y; s.z += b.z; s.w += b.w;
    ((float4*)g_H)[i] = s;
}

// ---------------- cluster: fused split-K CS reduce + softmax + top-8 --------
__global__ void cluster_kernel() {
    int wid = threadIdx.x >> 5, lane = threadIdx.x & 31;
    int pair = blockIdx.x * 8 + wid;
    int token = pair >> 2, g = pair & 3;

    int nc   = (g == 3) ? 128 : 64;
    int base = (g < 3) ? g * 64 : 192;
    const float* cs0 = g_csp + (size_t)token * 320 + base;
    const float* cs1 = cs0 + (size_t)TOKENS * 320;

    float v[4];
    #pragma unroll
    for (int j = 0; j < 4; j++) {
        int c = j * 32 + lane;
        v[j] = (c < nc) ? (cs0[c] + cs1[c]) : -INFINITY;
    }

    float m = fmaxf(fmaxf(v[0], v[1]), fmaxf(v[2], v[3]));
    #pragma unroll
    for (int o = 16; o; o >>= 1) m = fmaxf(m, __shfl_xor_sync(0xffffffffu, m, o));
    float ssum = 0.f;
    #pragma unroll
    for (int j = 0; j < 4; j++) ssum += expf(v[j] - m);
    #pragma unroll
    for (int o = 16; o; o >>= 1) ssum += __shfl_xor_sync(0xffffffffu, ssum, o);

    #pragma unroll
    for (int j = 0; j < 4; j++) {
        int c = j * 32 + lane;
        if (c < nc) atomicAdd(&g_csum[base + c], expf(v[j] - m) / ssum);
    }

    unsigned rm = 0;
    int mytop = 0;
    for (int it = 0; it < 8; it++) {
        unsigned long long best = 0ULL;
        #pragma unroll
        for (int j = 0; j < 4; j++) {
            if (!((rm >> j) & 1u)) {
                int c = j * 32 + lane;
                unsigned b = __float_as_uint(v[j]);
                unsigned u = (b & 0x80000000u) ? ~b : (b | 0x80000000u);
                unsigned long long k = (((unsigned long long)u) << 32) | (unsigned)(256 - c);
                if (k > best) best = k;
            }
        }
        #pragma unroll
        for (int o = 16; o; o >>= 1) {
            unsigned long long t2 = __shfl_xor_sync(0xffffffffu, best, o);
            if (t2 > best) best = t2;
        }
        int idx = 256 - (int)(best & 0xffffffffu);
        if (it == lane) mytop = idx;
        if ((idx & 31) == lane) rm |= 1u << (idx >> 5);
    }

    if (lane < 8) {
        g_topc[(size_t)pair * 8 + lane] = mytop;
        int pos = atomicAdd(&g_cnt[base + mytop], 1);
        g_list[(size_t)(base + mytop) * 2048 + pos] = token | (lane << 16);
    }
}

// ---------------- cluster-grouped score GEMM ----------------
__global__ void score_kernel() {
    __shared__ __align__(16) float As[64 * 64];
    __shared__ __align__(16) float Bs[64 * 64];
    __shared__ int s_tok[64];
    __shared__ int s_slot[64];

    int gc = blockIdx.x;
    int cnt = g_cnt[gc];
    int start = blockIdx.y * 64;
    if (start >= cnt) return;

    int g  = (gc < 64) ? 0 : (gc < 128) ? 1 : (gc < 192) ? 2 : 3;
    int cl = gc - ((g < 3) ? g * 64 : 192);
    int embbase = (g < 2) ? 0 : ((g == 2) ? 4096 : 8192);
    int nbase = embbase + cl * 64;

    int t = threadIdx.x;
    if (t < 64) {
        if (start + t < cnt) {
            int e = g_list[(size_t)gc * 2048 + start + t];
            s_tok[t] = e & 0xffff;
            s_slot[t] = e >> 16;
        } else {
            s_tok[t] = -1; s_slot[t] = 0;
        }
    }
    __syncthreads();

    int m = t & 63, c4 = t >> 6;
    int ty = t >> 4, tx = t & 15;

    unsigned long long acc[4][2];
    #pragma unroll
    for (int i = 0; i < 4; i++) { acc[i][0] = 0ULL; acc[i][1] = 0ULL; }

    int tok = s_tok[m];
    const float* hrow = (tok >= 0) ? (g_H + (size_t)tok * NH + g * 128) : g_embn;
    const float* erow = g_embn + (size_t)(nbase + m) * DS;

    for (int half = 0; half < 2; half++) {
        int kb = half * 64;
        #pragma unroll
        for (int i = 0; i < 4; i++) {
            int k0 = c4 * 4 + i * 16;
            float4 ve = *(const float4*)(erow + kb + k0);
            Bs[(k0 + 0) * 64 + m] = ve.x;
            Bs[(k0 + 1) * 64 + m] = ve.y;
            Bs[(k0 + 2) * 64 + m] = ve.z;
            Bs[(k0 + 3) * 64 + m] = ve.w;
            float4 vh = *(const float4*)(hrow + kb + k0);
            As[(k0 + 0) * 64 + m] = vh.x;
            As[(k0 + 1) * 64 + m] = vh.y;
            As[(k0 + 2) * 64 + m] = vh.z;
            As[(k0 + 3) * 64 + m] = vh.w;
        }
        __syncthreads();

        #pragma unroll 4
        for (int k = 0; k < 64; k++) {
            float a[4];
            *(float4*)a = *(const float4*)&As[k * 64 + ty * 4];
            ulonglong2 bb = *(const ulonglong2*)&Bs[k * 64 + tx * 4];
            #pragma unroll
            for (int i = 0; i < 4; i++) {
                unsigned long long ap = pk2(a[i]);
                fma2(acc[i][0], ap, bb.x);
                fma2(acc[i][1], ap, bb.y);
            }
        }
        __syncthreads();
    }

    #pragma unroll
    for (int i = 0; i < 4; i++) {
        int mm = ty * 4 + i;
        int tok2 = s_tok[mm];
        if (tok2 >= 0) {
            float2 p0 = upk(acc[i][0]);
            float2 p1 = upk(acc[i][1]);
            float4 v = make_float4(p0.x, p0.y, p1.x, p1.y);
            *(float4*)(g_scores + ((size_t)tok2 * 4 + g) * 512 + s_slot[mm] * 64 + tx * 4) = v;
        }
    }
}

// ---------------- gate + sparse output write (warp per pair) ----------------
__global__ void gate_out_kernel(float* __restrict__ out) {
    int wid = threadIdx.x >> 5, lane = threadIdx.x & 31;
    int pair = blockIdx.x * 8 + wid;
    int token = pair >> 2, g = pair & 3;
    int outbase = g * 4096;

    const float* srow = g_scores + (size_t)pair * 512;
    float tau = g_tau[pair];
    int tcl = (lane < 8) ? g_topc[(size_t)pair * 8 + lane] : 0;

    float raw[16];
    unsigned u[16];
    unsigned lmax = 0;
    #pragma unroll
    for (int i = 0; i < 16; i++) {
        raw[i] = srow[i * 32 + lane] - tau;
        unsigned b = __float_as_uint(raw[i]);
        u[i] = (b & 0x80000000u) ? ~b : (b | 0x80000000u);
        lmax = (u[i] > lmax) ? u[i] : lmax;
    }
    unsigned umax = __reduce_max_sync(0xffffffffu, lmax);

    unsigned lo = 0, hi = umax;
    while (lo < hi) {
        unsigned mid = lo + ((hi - lo + 1) >> 1);
        int c = 0;
        #pragma unroll
        for (int i = 0; i < 16; i++) c += (u[i] >= mid);
        if (__reduce_add_sync(0xffffffffu, (unsigned)c) >= MAXK) lo = mid;
        else hi = mid - 1;
    }
    unsigned tb = (lo & 0x80000000u) ? (lo ^ 0x80000000u) : ~lo;
    unsigned mb = (umax & 0x80000000u) ? (umax ^ 0x80000000u) : ~umax;
    float raw_thr = __uint_as_float(tb);
    float eg_thr = fgate(raw_thr);
    float eg_max = fgate(__uint_as_float(mb));

    bool full = (eg_thr <= 4e-7f);
    float cand_lo = full ? -INFINITY : (raw_thr - 2.5e-7f);

    float eg[16];
    float s = 0.f;
    #pragma unroll
    for (int i = 0; i < 16; i++) {
        float e = -1.f;
        if (raw[i] >= cand_lo) {
            float ev = fgate(raw[i]);
            if (ev >= eg_thr) { e = ev; s += ev; }
        }
        eg[i] = e;
    }
    #pragma unroll
    for (int o = 16; o; o >>= 1) s += __shfl_xor_sync(0xffffffffu, s, o);
    float r = tanhf(eg_max) / (s + 1e-8f);

    float* orow = out + (size_t)token * OUTW + outbase;
    #pragma unroll
    for (int i = 0; i < 16; i++) {
        int tc = __shfl_sync(0xffffffffu, tcl, i >> 1);
        if (eg[i] > 0.f) {
            float val = eg[i] * r;
            if (val > 0.f) {
                int col = tc * 64 + (i & 1) * 32 + lane;
                orow[col] = val;
                atomicAdd(&g_nmass[outbase + col], val);
            }
        }
    }
}

// ---------------- aux: parallel partial + write ----------------
__global__ void aux_partial_kernel() {
    int i = blockIdx.x * blockDim.x + threadIdx.x;
    int lane = threadIdx.x & 31, wid = threadIdx.x >> 5;
    double acc = 0.0;
    if (i < 320 + OUTW) {
        if (i < 320) {
            int nc = (i < 192) ? 64 : 128;
            double fr = (double)g_csum[i] / 2048.0;
            double d = fr - 1.0 / nc;
            acc = d * d * nc;
        } else {
            int j = i - 320;
            int N = (j < 12288) ? 4096 : 8192;
            double fr = (double)g_nmass[j] / 2048.0;
            double d = fr - 1.0 / N;
            acc = d * d * N;
        }
    }
    #pragma unroll
    for (int o = 16; o; o >>= 1) acc += __shfl_xor_sync(0xffffffffu, acc, o);
    __shared__ double rd[8];
    if (lane == 0) rd[wid] = acc;
    __syncthreads();
    if (threadIdx.x == 0) {
        double t = rd[0] + rd[1] + rd[2] + rd[3] + rd[4] + rd[5] + rd[6] + rd[7];
        atomicAdd(&g_aux, t);
    }
}

__global__ void aux_write_kernel(float* __restrict__ out, long long outsize) {
    out[outsize - 1] = (float)g_aux;
}

// ---------------- launch ----------------
extern "C" void kernel_launch(void* const* d_in, const int* in_sizes, int n_in,
                              void* d_out, int out_size) {
    const float* x    = (const float*)d_in[0];
    const float* emb  = (const float*)d_in[1];
    const float* Wa   = (const float*)d_in[2];
    const float* ba   = (const float*)d_in[3];
    const float* Wk   = (const float*)d_in[4];
    const float* bk   = (const float*)d_in[5];
    const float* Wta  = (const float*)d_in[6];
    const float* bta  = (const float*)d_in[7];
    const float* Wtk  = (const float*)d_in[8];
    const float* btk  = (const float*)d_in[9];
    const float* cqk  = (const float*)d_in[10];
    const float* cv   = (const float*)d_in[11];
    const float* cknw = (const float*)d_in[12];
    float* out = (float*)d_out;

    norm_kernel<<<(NTOT + NCET) / 8, 256>>>(emb, cqk, cv, cknw);
    cebig_kernel<<<(512 * 320 + 255) / 256, 256>>>(ba, bk, Wta, bta, Wtk, btk);
    zerofill_kernel<<<5120, 256>>>((float4*)out);
    sgemm0_kernel<<<dim3(16, 4, SK0), 256>>>(x, Wa, Wk);   // 4th launch -> profiled
    reduceH_kernel<<<TOKENS * NH / 4 / 256, 256>>>();
    tau_kernel<<<TOKENS / 8, 256>>>(x);
    sgemm1_kernel<<<dim3(16, 5, SK1), 256>>>();
    cluster_kernel<<<TOKENS * 4 / 8, 256>>>();
    score_kernel<<<dim3(320, 32), 256>>>();
    gate_out_kernel<<<TOKENS * 4 / 8, 256>>>(out);
    aux_partial_kernel<<<(320 + OUTW + 255) / 256, 256>>>();
    aux_write_kernel<<<1, 1>>>(out, (long long)out_size);
}

// round 13
// speedup vs baseline: 1.1492x; 1.0816x over previous
#include <cuda_runtime.h>
#include <math.h>
#include <stdint.h>

// ---------------- problem constants ----------------
#define TOKENS 2048
#define DM     2048
#define DS     128
#define NH     512
#define NTOT   16384
#define NCET   256
#define OUTW   20480
#define MAXK   32
#define SK0    4

// ---------------- device scratch ----------------
__device__ float  g_H[TOKENS * NH];
__device__ float  g_Hp[SK0 * TOKENS * NH];
__device__ float  g_b[NH];
__device__ float4 g_wtau4[DM];
__device__ float  g_btau[4];
__device__ float  g_tau[TOKENS * 4];
__device__ float  g_embn[NTOT * DS];
__device__ float  g_ce[NCET * DS];
__device__ float  g_csAll[TOKENS * 320];
__device__ float  g_csum[320];
__device__ float  g_nmass[OUTW];
__device__ int    g_cnt[320];
__device__ int    g_list[320 * 2048];
__device__ int    g_topc[TOKENS * 4 * 8];
__device__ float  g_scores[TOKENS * 4 * 512];
__device__ double g_aux;

// ---------------- f32x2 packed helpers ----------------
__device__ __forceinline__ unsigned long long pk2(float x) {
    unsigned long long r;
    asm("mov.b64 %0, {%1, %1};" : "=l"(r) : "f"(x));
    return r;
}
__device__ __forceinline__ void fma2(unsigned long long& c,
                                     unsigned long long a, unsigned long long b) {
    asm("fma.rn.f32x2 %0, %1, %2, %0;" : "+l"(c) : "l"(a), "l"(b));
}
__device__ __forceinline__ float2 upk(unsigned long long p) {
    float2 f;
    asm("mov.b64 {%0, %1}, %2;" : "=f"(f.x), "=f"(f.y) : "l"(p));
    return f;
}

// gate nonlinearity (matches reference float path)
__device__ __forceinline__ float fgate(float raw) {
    float gt = (raw > 0.f) ? raw : 1e-8f * expf(raw);
    return expf(gt) - 1.0f;
}

// ---------------- prep: embedding norm (blocks 0..2079) + init/pack --------
#define NORM_BLOCKS ((NTOT + NCET) / 8)     // 2080
__global__ void prep_kernel(const float* __restrict__ emb,
                            const float* __restrict__ cqk,
                            const float* __restrict__ cv,
                            const float* __restrict__ cknow,
                            const float* __restrict__ ba, const float* __restrict__ bk,
                            const float* __restrict__ Wta, const float* __restrict__ bta,
                            const float* __restrict__ Wtk, const float* __restrict__ btk) {
    if (blockIdx.x < NORM_BLOCKS) {
        int wid = threadIdx.x >> 5, lane = threadIdx.x & 31;
        int r = blockIdx.x * 8 + wid;
        const float* src;
        if (r < NTOT) {
            src = emb + (size_t)r * DS;
        } else {
            int c = r - NTOT;
            if (c < 64)       src = cqk + (size_t)c * DS;
            else if (c < 128) src = cv + (size_t)(c - 64) * DS;
            else              src = cknow + (size_t)(c - 128) * DS;
        }
        float4 v = ((const float4*)src)[lane];
        float ss = v.x * v.x + v.y * v.y + v.z * v.z + v.w * v.w;
        #pragma unroll
        for (int o = 16; o; o >>= 1) ss += __shfl_xor_sync(0xffffffffu, ss, o);
        float invn = 1.0f / (sqrtf(ss) + 1e-8f);
        float4 ov = make_float4(v.x * invn, v.y * invn, v.z * invn, v.w * invn);
        if (r < NTOT) ((float4*)(g_embn + (size_t)r * DS))[lane] = ov;
        else          ((float4*)(g_ce + (size_t)(r - NTOT) * DS))[lane] = ov;
    } else {
        int i = (blockIdx.x - NORM_BLOCKS) * 256 + threadIdx.x;   // 0..20479
        if (i < 320) { g_csum[i] = 0.f; g_cnt[i] = 0; }
        if (i < OUTW) g_nmass[i] = 0.f;
        if (i < NH) g_b[i] = (i < 384) ? ba[i] : bk[i - 384];
        if (i < DM)
            g_wtau4[i] = make_float4(Wta[i * 3 + 0], Wta[i * 3 + 1], Wta[i * 3 + 2], Wtk[i]);
        if (i == 0) {
            g_btau[0] = bta[0]; g_btau[1] = bta[1]; g_btau[2] = bta[2]; g_btau[3] = btk[0];
            g_aux = 0.0;
        }
    }
}

// ---------------- zero the whole output tensor ----------------
__global__ void zerofill_kernel(float4* __restrict__ out4) {
    int i = blockIdx.x * blockDim.x + threadIdx.x;
    const int stride = 5120 * 256;
    float4 z = make_float4(0.f, 0.f, 0.f, 0.f);
    #pragma unroll
    for (int r = 0; r < 8; r++) out4[i + r * stride] = z;
}

// ---------------- tau ----------------
__global__ void tau_kernel(const float* __restrict__ x) {
    int wid = threadIdx.x >> 5, lane = threadIdx.x & 31;
    int token = blockIdx.x * 8 + wid;
    const float* xr = x + (size_t)token * DM;
    float a0 = 0.f, a1 = 0.f, a2 = 0.f, a3 = 0.f;
    #pragma unroll
    for (int q = 0; q < 16; q++) {
        int k0 = q * 128 + lane * 4;
        float4 xv = *(const float4*)(xr + k0);
        float4 w0 = g_wtau4[k0 + 0];
        float4 w1 = g_wtau4[k0 + 1];
        float4 w2 = g_wtau4[k0 + 2];
        float4 w3 = g_wtau4[k0 + 3];
        a0 = fmaf(xv.x, w0.x, fmaf(xv.y, w1.x, fmaf(xv.z, w2.x, fmaf(xv.w, w3.x, a0))));
        a1 = fmaf(xv.x, w0.y, fmaf(xv.y, w1.y, fmaf(xv.z, w2.y, fmaf(xv.w, w3.y, a1))));
        a2 = fmaf(xv.x, w0.z, fmaf(xv.y, w1.z, fmaf(xv.z, w2.z, fmaf(xv.w, w3.z, a2))));
        a3 = fmaf(xv.x, w0.w, fmaf(xv.y, w1.w, fmaf(xv.z, w2.w, fmaf(xv.w, w3.w, a3))));
    }
    #pragma unroll
    for (int o = 16; o; o >>= 1) {
        a0 += __shfl_xor_sync(0xffffffffu, a0, o);
        a1 += __shfl_xor_sync(0xffffffffu, a1, o);
        a2 += __shfl_xor_sync(0xffffffffu, a2, o);
        a3 += __shfl_xor_sync(0xffffffffu, a3, o);
    }
    if (lane == 0) {
        g_tau[token * 4 + 0] = a0 + g_btau[0];
        g_tau[token * 4 + 1] = a1 + g_btau[1];
        g_tau[token * 4 + 2] = a2 + g_btau[2];
        g_tau[token * 4 + 3] = a3 + g_btau[3];
    }
}

// ---------------- GEMM0: double-buffered 8x8 FFMA2, direct Wa/Wk reads ------
#define LDT 132

#define G0_LOAD(KOFF)                                            \
    pa0 = *(const float4*)(Ap + (KOFF));                         \
    pa1 = *(const float4*)(Ap + (KOFF) + 4);                     \
    pb0 = *(const float4*)(Bp + (size_t)(KOFF) * ldb);           \
    pb1 = *(const float4*)(Bp + (size_t)(KOFF) * ldb + 4);

#define G0_STORE(AS, BS)                                         \
    AS[(ak + 0) * LDT + am] = pa0.x;                             \
    AS[(ak + 1) * LDT + am] = pa0.y;                             \
    AS[(ak + 2) * LDT + am] = pa0.z;                             \
    AS[(ak + 3) * LDT + am] = pa0.w;                             \
    AS[(ak + 4) * LDT + am] = pa1.x;                             \
    AS[(ak + 5) * LDT + am] = pa1.y;                             \
    AS[(ak + 6) * LDT + am] = pa1.z;                             \
    AS[(ak + 7) * LDT + am] = pa1.w;                             \
    *(float4*)&BS[bkr * LDT + bn0] = pb0;                        \
    *(float4*)&BS[bkr * LDT + bn0 + 4] = pb1;

#define G0_COMPUTE(AS, BS)                                       \
    _Pragma("unroll")                                            \
    for (int kk = 0; kk < 16; kk++) {                            \
        ulonglong2 a01 = *(const ulonglong2*)&AS[kk * LDT + ty * 4];       \
        ulonglong2 a23 = *(const ulonglong2*)&AS[kk * LDT + 64 + ty * 4];  \
        float4 b0 = *(const float4*)&BS[kk * LDT + tx * 4];                \
        float4 b1 = *(const float4*)&BS[kk * LDT + 64 + tx * 4];           \
        unsigned long long bp[8];                                          \
        bp[0] = pk2(b0.x); bp[1] = pk2(b0.y); bp[2] = pk2(b0.z); bp[3] = pk2(b0.w); \
        bp[4] = pk2(b1.x); bp[5] = pk2(b1.y); bp[6] = pk2(b1.z); bp[7] = pk2(b1.w); \
        _Pragma("unroll")                                        \
        for (int j = 0; j < 8; j++) {                            \
            fma2(acc[0][j], a01.x, bp[j]);                       \
            fma2(acc[1][j], a01.y, bp[j]);                       \
            fma2(acc[2][j], a23.x, bp[j]);                       \
            fma2(acc[3][j], a23.y, bp[j]);                       \
        }                                                        \
    }

__global__ __launch_bounds__(256, 2) void sgemm0_kernel(const float* __restrict__ x,
                                                        const float* __restrict__ Wa,
                                                        const float* __restrict__ Wk) {
    __shared__ __align__(16) float As0[16 * LDT];
    __shared__ __align__(16) float Bs0[16 * LDT];
    __shared__ __align__(16) float As1[16 * LDT];
    __shared__ __align__(16) float Bs1[16 * LDT];

    int bm = blockIdx.x * 128;
    int bn_c = blockIdx.y * 128;
    int kbeg = blockIdx.z * (DM / SK0);
    float* C = g_Hp + (size_t)blockIdx.z * TOKENS * NH;

    int tid = threadIdx.x;
    int am = tid >> 1, ak = (tid & 1) << 3;
    int bkr = tid >> 4, bn0 = (tid & 15) << 3;
    int ty = tid >> 4, tx = tid & 15;

    const float* Ap = x + (size_t)(bm + am) * DM + kbeg + ak;
    const float* Bp; int ldb;
    if (blockIdx.y < 3) { Bp = Wa + (size_t)(kbeg + bkr) * 384 + bn_c + bn0; ldb = 384; }
    else                { Bp = Wk + (size_t)(kbeg + bkr) * 128 + bn0;        ldb = 128; }

    unsigned long long acc[4][8];
    #pragma unroll
    for (int i = 0; i < 4; i++)
        #pragma unroll
        for (int j = 0; j < 8; j++) acc[i][j] = 0ULL;

    float4 pa0, pa1, pb0, pb1;
    G0_LOAD(0);
    G0_STORE(As0, Bs0);
    __syncthreads();

    for (int kt = 0; kt < DM / SK0; kt += 32) {
        G0_LOAD(kt + 16);
        G0_COMPUTE(As0, Bs0);
        G0_STORE(As1, Bs1);
        __syncthreads();

        if (kt + 32 < DM / SK0) { G0_LOAD(kt + 32); }
        G0_COMPUTE(As1, Bs1);
        if (kt + 32 < DM / SK0) { G0_STORE(As0, Bs0); }
        __syncthreads();
    }

    #pragma unroll
    for (int mi = 0; mi < 4; mi++) {
        int row = bm + ((mi < 2) ? (ty * 4 + mi * 2) : (64 + ty * 4 + (mi - 2) * 2));
        #pragma unroll
        for (int j = 0; j < 8; j++) {
            int col = bn_c + ((j < 4) ? (tx * 4 + j) : (64 + tx * 4 + (j - 4)));
            float2 v = upk(acc[mi][j]);
            C[(size_t)row * NH + col] = v.x;
            C[(size_t)(row + 1) * NH + col] = v.y;
        }
    }
}

// ---------------- reduce split-K partials for H (adds bias) ----------------
__global__ void reduceH_kernel() {
    int i = blockIdx.x * blockDim.x + threadIdx.x;
    const float4* p = (const float4*)g_Hp;
    constexpr int Q = TOKENS * NH / 4;
    float4 s = p[i];
    #pragma unroll
    for (int z = 1; z < SK0; z++) {
        float4 t = p[i + z * Q];
        s.x += t.x; s.y += t.y; s.z += t.z; s.w += t.w;
    }
    float4 b = ((const float4*)g_b)[i & 127];
    s.x += b.x; s.y += b.y; s.z += b.z; s.w += b.w;
    ((float4*)g_H)[i] = s;
}

// ---------------- block-diagonal cluster-score GEMM ----------------
// grid (32, 5): 64 tokens x 64 cluster-cols x K=128.
// tile map: by -> (H k-base, ce row base, csAll col base)
__global__ void csgemm_kernel() {
    __shared__ __align__(16) float As[64 * 64];   // [k][m] token tile
    __shared__ __align__(16) float Bs[64 * 64];   // [k][n] ce tile

    int byt = blockIdx.y;
    int kb0  = (byt == 0) ? 0 : (byt == 1) ? 128 : (byt == 2) ? 256 : 384;
    int cr0  = (byt < 2) ? 0 : (byt == 2) ? 64 : (byt == 3) ? 128 : 192;
    int base = byt * 64;
    int tok0 = blockIdx.x * 64;

    int t = threadIdx.x;
    int m = t & 63, c4 = t >> 6;
    int ty = t >> 4, tx = t & 15;

    unsigned long long acc[4][2];
    #pragma unroll
    for (int i = 0; i < 4; i++) { acc[i][0] = 0ULL; acc[i][1] = 0ULL; }

    const float* hrow = g_H + (size_t)(tok0 + m) * NH + kb0;
    const float* erow = g_ce + (size_t)(cr0 + m) * DS;

    for (int half = 0; half < 2; half++) {
        int kb = half * 64;
        #pragma unroll
        for (int i = 0; i < 4; i++) {
            int k0 = c4 * 4 + i * 16;
            float4 ve = *(const float4*)(erow + kb + k0);
            Bs[(k0 + 0) * 64 + m] = ve.x;
            Bs[(k0 + 1) * 64 + m] = ve.y;
            Bs[(k0 + 2) * 64 + m] = ve.z;
            Bs[(k0 + 3) * 64 + m] = ve.w;
            float4 vh = *(const float4*)(hrow + kb + k0);
            As[(k0 + 0) * 64 + m] = vh.x;
            As[(k0 + 1) * 64 + m] = vh.y;
            As[(k0 + 2) * 64 + m] = vh.z;
            As[(k0 + 3) * 64 + m] = vh.w;
        }
        __syncthreads();

        #pragma unroll 4
        for (int k = 0; k < 64; k++) {
            float a[4];
            *(float4*)a = *(const float4*)&As[k * 64 + ty * 4];
            ulonglong2 bb = *(const ulonglong2*)&Bs[k * 64 + tx * 4];
            #pragma unroll
            for (int i = 0; i < 4; i++) {
                unsigned long long ap = pk2(a[i]);
                fma2(acc[i][0], ap, bb.x);
                fma2(acc[i][1], ap, bb.y);
            }
        }
        __syncthreads();
    }

    #pragma unroll
    for (int i = 0; i < 4; i++) {
        int mm = ty * 4 + i;
        float2 p0 = upk(acc[i][0]);
        float2 p1 = upk(acc[i][1]);
        float4 v = make_float4(p0.x, p0.y, p1.x, p1.y);
        *(float4*)(g_csAll + (size_t)(tok0 + mm) * 320 + base + tx * 4) = v;
    }
}

// ---------------- cluster: softmax + top-8 + list build ----------------
__global__ void cluster_kernel() {
    int wid = threadIdx.x >> 5, lane = threadIdx.x & 31;
    int pair = blockIdx.x * 8 + wid;
    int token = pair >> 2, g = pair & 3;

    int nc   = (g == 3) ? 128 : 64;
    int base = (g < 3) ? g * 64 : 192;
    const float* cs = g_csAll + (size_t)token * 320 + base;

    float v[4];
    #pragma unroll
    for (int j = 0; j < 4; j++) {
        int c = j * 32 + lane;
        v[j] = (c < nc) ? cs[c] : -INFINITY;
    }

    float m = fmaxf(fmaxf(v[0], v[1]), fmaxf(v[2], v[3]));
    #pragma unroll
    for (int o = 16; o; o >>= 1) m = fmaxf(m, __shfl_xor_sync(0xffffffffu, m, o));
    float ssum = 0.f;
    #pragma unroll
    for (int j = 0; j < 4; j++) ssum += expf(v[j] - m);
    #pragma unroll
    for (int o = 16; o; o >>= 1) ssum += __shfl_xor_sync(0xffffffffu, ssum, o);

    #pragma unroll
    for (int j = 0; j < 4; j++) {
        int c = j * 32 + lane;
        if (c < nc) atomicAdd(&g_csum[base + c], expf(v[j] - m) / ssum);
    }

    unsigned rm = 0;
    int mytop = 0;
    for (int it = 0; it < 8; it++) {
        unsigned long long best = 0ULL;
        #pragma unroll
        for (int j = 0; j < 4; j++) {
            if (!((rm >> j) & 1u)) {
                int c = j * 32 + lane;
                unsigned b = __float_as_uint(v[j]);
                unsigned u = (b & 0x80000000u) ? ~b : (b | 0x80000000u);
                unsigned long long k = (((unsigned long long)u) << 32) | (unsigned)(256 - c);
                if (k > best) best = k;
            }
        }
        #pragma unroll
        for (int o = 16; o; o >>= 1) {
            unsigned long long t2 = __shfl_xor_sync(0xffffffffu, best, o);
            if (t2 > best) best = t2;
        }
        int idx = 256 - (int)(best & 0xffffffffu);
        if (it == lane) mytop = idx;
        if ((idx & 31) == lane) rm |= 1u << (idx >> 5);
    }

    if (lane < 8) {
        g_topc[(size_t)pair * 8 + lane] = mytop;
        int pos = atomicAdd(&g_cnt[base + mytop], 1);
        g_list[(size_t)(base + mytop) * 2048 + pos] = token | (lane << 16);
    }
}

// ---------------- cluster-grouped score GEMM (chunk-strided) ----------------
// grid (320, 8): each block loops over chunks start = by*64, by*64+512, ...
__global__ void score_kernel() {
    __shared__ __align__(16) float As[64 * 64];
    __shared__ __align__(16) float Bs[64 * 64];
    __shared__ int s_tok[64];
    __shared__ int s_slot[64];

    int gc = blockIdx.x;
    int cnt = g_cnt[gc];

    int g  = (gc < 64) ? 0 : (gc < 128) ? 1 : (gc < 192) ? 2 : 3;
    int cl = gc - ((g < 3) ? g * 64 : 192);
    int embbase = (g < 2) ? 0 : ((g == 2) ? 4096 : 8192);
    int nbase = embbase + cl * 64;

    int t = threadIdx.x;
    int m = t & 63, c4 = t >> 6;
    int ty = t >> 4, tx = t & 15;
    const float* erow = g_embn + (size_t)(nbase + m) * DS;

    for (int start = blockIdx.y * 64; start < cnt; start += 8 * 64) {
        __syncthreads();    // protect s_tok / smem reuse from previous chunk
        if (t < 64) {
            if (start + t < cnt) {
                int e = g_list[(size_t)gc * 2048 + start + t];
                s_tok[t] = e & 0xffff;
                s_slot[t] = e >> 16;
            } else {
                s_tok[t] = -1; s_slot[t] = 0;
            }
        }
        __syncthreads();

        unsigned long long acc[4][2];
        #pragma unroll
        for (int i = 0; i < 4; i++) { acc[i][0] = 0ULL; acc[i][1] = 0ULL; }

        int tok = s_tok[m];
        const float* hrow = (tok >= 0) ? (g_H + (size_t)tok * NH + g * 128) : g_embn;

        for (int half = 0; half < 2; half++) {
            int kb = half * 64;
            #pragma unroll
            for (int i = 0; i < 4; i++) {
                int k0 = c4 * 4 + i * 16;
                float4 ve = *(const float4*)(erow + kb + k0);
                Bs[(k0 + 0) * 64 + m] = ve.x;
                Bs[(k0 + 1) * 64 + m] = ve.y;
                Bs[(k0 + 2) * 64 + m] = ve.z;
                Bs[(k0 + 3) * 64 + m] = ve.w;
                float4 vh = *(const float4*)(hrow + kb + k0);
                As[(k0 + 0) * 64 + m] = vh.x;
                As[(k0 + 1) * 64 + m] = vh.y;
                As[(k0 + 2) * 64 + m] = vh.z;
                As[(k0 + 3) * 64 + m] = vh.w;
            }
            __syncthreads();

            #pragma unroll 4
            for (int k = 0; k < 64; k++) {
                float a[4];
                *(float4*)a = *(const float4*)&As[k * 64 + ty * 4];
                ulonglong2 bb = *(const ulonglong2*)&Bs[k * 64 + tx * 4];
                #pragma unroll
                for (int i = 0; i < 4; i++) {
                    unsigned long long ap = pk2(a[i]);
                    fma2(acc[i][0], ap, bb.x);
                    fma2(acc[i][1], ap, bb.y);
                }
            }
            __syncthreads();
        }

        #pragma unroll
        for (int i = 0; i < 4; i++) {
            int mm = ty * 4 + i;
            int tok2 = s_tok[mm];
            if (tok2 >= 0) {
                float2 p0 = upk(acc[i][0]);
                float2 p1 = upk(acc[i][1]);
                float4 v = make_float4(p0.x, p0.y, p1.x, p1.y);
                *(float4*)(g_scores + ((size_t)tok2 * 4 + g) * 512 + s_slot[mm] * 64 + tx * 4) = v;
            }
        }
    }
}

// ---------------- gate + sparse output write (warp per pair) ----------------
__global__ void gate_out_kernel(float* __restrict__ out) {
    int wid = threadIdx.x >> 5, lane = threadIdx.x & 31;
    int pair = blockIdx.x * 8 + wid;
    int token = pair >> 2, g = pair & 3;
    int outbase = g * 4096;

    const float* srow = g_scores + (size_t)pair * 512;
    float tau = g_tau[pair];
    int tcl = (lane < 8) ? g_topc[(size_t)pair * 8 + lane] : 0;

    float raw[16];
    unsigned u[16];
    unsigned lmax = 0;
    #pragma unroll
    for (int i = 0; i < 16; i++) {
        raw[i] = srow[i * 32 + lane] - tau;
        unsigned b = __float_as_uint(raw[i]);
        u[i] = (b & 0x80000000u) ? ~b : (b | 0x80000000u);
        lmax = (u[i] > lmax) ? u[i] : lmax;
    }
    unsigned umax = __reduce_max_sync(0xffffffffu, lmax);

    unsigned lo = 0, hi = umax;
    while (lo < hi) {
        unsigned mid = lo + ((hi - lo + 1) >> 1);
        int c = 0;
        #pragma unroll
        for (int i = 0; i < 16; i++) c += (u[i] >= mid);
        if (__reduce_add_sync(0xffffffffu, (unsigned)c) >= MAXK) lo = mid;
        else hi = mid - 1;
    }
    unsigned tb = (lo & 0x80000000u) ? (lo ^ 0x80000000u) : ~lo;
    unsigned mb = (umax & 0x80000000u) ? (umax ^ 0x80000000u) : ~umax;
    float raw_thr = __uint_as_float(tb);
    float eg_thr = fgate(raw_thr);
    float eg_max = fgate(__uint_as_float(mb));

    bool full = (eg_thr <= 4e-7f);
    float cand_lo = full ? -INFINITY : (raw_thr - 2.5e-7f);

    float eg[16];
    float s = 0.f;
    #pragma unroll
    for (int i = 0; i < 16; i++) {
        float e = -1.f;
        if (raw[i] >= cand_lo) {
            float ev = fgate(raw[i]);
            if (ev >= eg_thr) { e = ev; s += ev; }
        }
        eg[i] = e;
    }
    #pragma unroll
    for (int o = 16; o; o >>= 1) s += __shfl_xor_sync(0xffffffffu, s, o);
    float r = tanhf(eg_max) / (s + 1e-8f);

    float* orow = out + (size_t)token * OUTW + outbase;
    #pragma unroll
    for (int i = 0; i < 16; i++) {
        int tc = __shfl_sync(0xffffffffu, tcl, i >> 1);
        if (eg[i] > 0.f) {
            float val = eg[i] * r;
            if (val > 0.f) {
                int col = tc * 64 + (i & 1) * 32 + lane;
                orow[col] = val;
                atomicAdd(&g_nmass[outbase + col], val);
            }
        }
    }
}

// ---------------- aux: parallel partial + write ----------------
__global__ void aux_partial_kernel() {
    int i = blockIdx.x * blockDim.x + threadIdx.x;
    int lane = threadIdx.x & 31, wid = threadIdx.x >> 5;
    double acc = 0.0;
    if (i < 320 + OUTW) {
        if (i < 320) {
            int nc = (i < 192) ? 64 : 128;
            double fr = (double)g_csum[i] / 2048.0;
            double d = fr - 1.0 / nc;
            acc = d * d * nc;
        } else {
            int j = i - 320;
            int N = (j < 12288) ? 4096 : 8192;
            double fr = (double)g_nmass[j] / 2048.0;
            double d = fr - 1.0 / N;
            acc = d * d * N;
        }
    }
    #pragma unroll
    for (int o = 16; o; o >>= 1) acc += __shfl_xor_sync(0xffffffffu, acc, o);
    __shared__ double rd[8];
    if (lane == 0) rd[wid] = acc;
    __syncthreads();
    if (threadIdx.x == 0) {
        double t = rd[0] + rd[1] + rd[2] + rd[3] + rd[4] + rd[5] + rd[6] + rd[7];
        atomicAdd(&g_aux, t);
    }
}

__global__ void aux_write_kernel(float* __restrict__ out, long long outsize) {
    out[outsize - 1] = (float)g_aux;
}

// ---------------- launch ----------------
extern "C" void kernel_launch(void* const* d_in, const int* in_sizes, int n_in,
                              void* d_out, int out_size) {
    const float* x    = (const float*)d_in[0];
    const float* emb  = (const float*)d_in[1];
    const float* Wa   = (const float*)d_in[2];
    const float* ba   = (const float*)d_in[3];
    const float* Wk   = (const float*)d_in[4];
    const float* bk   = (const float*)d_in[5];
    const float* Wta  = (const float*)d_in[6];
    const float* bta  = (const float*)d_in[7];
    const float* Wtk  = (const float*)d_in[8];
    const float* btk  = (const float*)d_in[9];
    const float* cqk  = (const float*)d_in[10];
    const float* cv   = (const float*)d_in[11];
    const float* cknw = (const float*)d_in[12];
    float* out = (float*)d_out;

    prep_kernel<<<NORM_BLOCKS + OUTW / 256, 256>>>(emb, cqk, cv, cknw,
                                                   ba, bk, Wta, bta, Wtk, btk);
    zerofill_kernel<<<5120, 256>>>((float4*)out);
    tau_kernel<<<TOKENS / 8, 256>>>(x);
    sgemm0_kernel<<<dim3(16, 4, SK0), 256>>>(x, Wa, Wk);   // 4th launch -> profiled
    reduceH_kernel<<<TOKENS * NH / 4 / 256, 256>>>();
    csgemm_kernel<<<dim3(32, 5), 256>>>();
    cluster_kernel<<<TOKENS * 4 / 8, 256>>>();
    score_kernel<<<dim3(320, 8), 256>>>();
    gate_out_kernel<<<TOKENS * 4 / 8, 256>>>(out);
    aux_partial_kernel<<<(320 + OUTW + 255) / 256, 256>>>();
    aux_write_kernel<<<1, 1>>>(out, (long long)out_size);
}

// round 16
// speedup vs baseline: 1.2047x; 1.0484x over previous
#include <cuda_runtime.h>
#include <math.h>
#include <stdint.h>

// ---------------- problem constants ----------------
#define TOKENS 2048
#define DM     2048
#define DS     128
#define NH     512
#define NTOT   16384
#define NCET   256
#define OUTW   20480
#define MAXK   32
#define SK0    4

// ---------------- device scratch ----------------
__device__ float  g_H[TOKENS * NH];
__device__ float  g_Hp[SK0 * TOKENS * NH];
__device__ float  g_b[NH];
__device__ float  g_tau[TOKENS * 4];
__device__ float  g_embn[NTOT * DS];
__device__ float  g_ce[NCET * DS];
__device__ float  g_csAll[TOKENS * 320];
__device__ float  g_csum[320];
__device__ float  g_nmass[OUTW];
__device__ int    g_cnt[320];
__device__ int    g_list[320 * 2048];
__device__ int    g_topc[TOKENS * 4 * 8];
__device__ float  g_scores[TOKENS * 4 * 512];
__device__ double g_aux;

// ---------------- f32x2 packed helpers ----------------
__device__ __forceinline__ unsigned long long pk2(float x) {
    unsigned long long r;
    asm("mov.b64 %0, {%1, %1};" : "=l"(r) : "f"(x));
    return r;
}
__device__ __forceinline__ void fma2(unsigned long long& c,
                                     unsigned long long a, unsigned long long b) {
    asm("fma.rn.f32x2 %0, %1, %2, %0;" : "+l"(c) : "l"(a), "l"(b));
}
__device__ __forceinline__ float2 upk(unsigned long long p) {
    float2 f;
    asm("mov.b64 {%0, %1}, %2;" : "=f"(f.x), "=f"(f.y) : "l"(p));
    return f;
}

// gate nonlinearity (matches reference float path)
__device__ __forceinline__ float fgate(float raw) {
    float gt = (raw > 0.f) ? raw : 1e-8f * expf(raw);
    return expf(gt) - 1.0f;
}

// ---------------- prep: embedding norm (blocks 0..2079) + init/pack --------
#define NORM_BLOCKS ((NTOT + NCET) / 8)     // 2080
__global__ void prep_kernel(const float* __restrict__ emb,
                            const float* __restrict__ cqk,
                            const float* __restrict__ cv,
                            const float* __restrict__ cknow,
                            const float* __restrict__ ba, const float* __restrict__ bk) {
    if (blockIdx.x < NORM_BLOCKS) {
        int wid = threadIdx.x >> 5, lane = threadIdx.x & 31;
        int r = blockIdx.x * 8 + wid;
        const float* src;
        if (r < NTOT) {
            src = emb + (size_t)r * DS;
        } else {
            int c = r - NTOT;
            if (c < 64)       src = cqk + (size_t)c * DS;
            else if (c < 128) src = cv + (size_t)(c - 64) * DS;
            else              src = cknow + (size_t)(c - 128) * DS;
        }
        float4 v = ((const float4*)src)[lane];
        float ss = v.x * v.x + v.y * v.y + v.z * v.z + v.w * v.w;
        #pragma unroll
        for (int o = 16; o; o >>= 1) ss += __shfl_xor_sync(0xffffffffu, ss, o);
        float invn = 1.0f / (sqrtf(ss) + 1e-8f);
        float4 ov = make_float4(v.x * invn, v.y * invn, v.z * invn, v.w * invn);
        if (r < NTOT) ((float4*)(g_embn + (size_t)r * DS))[lane] = ov;
        else          ((float4*)(g_ce + (size_t)(r - NTOT) * DS))[lane] = ov;
    } else {
        int i = (blockIdx.x - NORM_BLOCKS) * 256 + threadIdx.x;   // 0..20479
        if (i < 320) { g_csum[i] = 0.f; g_cnt[i] = 0; }
        if (i < OUTW) g_nmass[i] = 0.f;
        if (i < NH) g_b[i] = (i < 384) ? ba[i] : bk[i - 384];
        if (i == 0) g_aux = 0.0;
    }
}

// ---------------- tau: direct Wta/Wtk reads, warp per token ----------------
__global__ void tau_kernel(const float* __restrict__ x,
                           const float* __restrict__ Wta, const float* __restrict__ Wtk,
                           const float* __restrict__ bta, const float* __restrict__ btk) {
    int wid = threadIdx.x >> 5, lane = threadIdx.x & 31;
    int token = blockIdx.x * 8 + wid;
    const float* xr = x + (size_t)token * DM;
    float a0 = 0.f, a1 = 0.f, a2 = 0.f, a3 = 0.f;
    #pragma unroll
    for (int q = 0; q < 16; q++) {
        int k0 = q * 128 + lane * 4;
        float4 xv = *(const float4*)(xr + k0);
        const float4* wp = (const float4*)(Wta + (size_t)3 * k0);
        float4 t0 = wp[0], t1 = wp[1], t2 = wp[2];
        float4 wk = *(const float4*)(Wtk + k0);
        a0 = fmaf(xv.x, t0.x, fmaf(xv.y, t0.w, fmaf(xv.z, t1.z, fmaf(xv.w, t2.y, a0))));
        a1 = fmaf(xv.x, t0.y, fmaf(xv.y, t1.x, fmaf(xv.z, t1.w, fmaf(xv.w, t2.z, a1))));
        a2 = fmaf(xv.x, t0.z, fmaf(xv.y, t1.y, fmaf(xv.z, t2.x, fmaf(xv.w, t2.w, a2))));
        a3 = fmaf(xv.x, wk.x, fmaf(xv.y, wk.y, fmaf(xv.z, wk.z, fmaf(xv.w, wk.w, a3))));
    }
    #pragma unroll
    for (int o = 16; o; o >>= 1) {
        a0 += __shfl_xor_sync(0xffffffffu, a0, o);
        a1 += __shfl_xor_sync(0xffffffffu, a1, o);
        a2 += __shfl_xor_sync(0xffffffffu, a2, o);
        a3 += __shfl_xor_sync(0xffffffffu, a3, o);
    }
    if (lane == 0) {
        g_tau[token * 4 + 0] = a0 + bta[0];
        g_tau[token * 4 + 1] = a1 + bta[1];
        g_tau[token * 4 + 2] = a2 + bta[2];
        g_tau[token * 4 + 3] = a3 + btk[0];
    }
}

// ---------------- GEMM0: double-buffered 8x8 FFMA2, direct Wa/Wk reads ------
#define LDT 132

#define G0_LOAD(KOFF)                                            \
    pa0 = *(const float4*)(Ap + (KOFF));                         \
    pa1 = *(const float4*)(Ap + (KOFF) + 4);                     \
    pb0 = *(const float4*)(Bp + (size_t)(KOFF) * ldb);           \
    pb1 = *(const float4*)(Bp + (size_t)(KOFF) * ldb + 4);

#define G0_STORE(AS, BS)                                         \
    AS[(ak + 0) * LDT + am] = pa0.x;                             \
    AS[(ak + 1) * LDT + am] = pa0.y;                             \
    AS[(ak + 2) * LDT + am] = pa0.z;                             \
    AS[(ak + 3) * LDT + am] = pa0.w;                             \
    AS[(ak + 4) * LDT + am] = pa1.x;                             \
    AS[(ak + 5) * LDT + am] = pa1.y;                             \
    AS[(ak + 6) * LDT + am] = pa1.z;                             \
    AS[(ak + 7) * LDT + am] = pa1.w;                             \
    *(float4*)&BS[bkr * LDT + bn0] = pb0;                        \
    *(float4*)&BS[bkr * LDT + bn0 + 4] = pb1;

#define G0_COMPUTE(AS, BS)                                       \
    _Pragma("unroll")                                            \
    for (int kk = 0; kk < 16; kk++) {                            \
        ulonglong2 a01 = *(const ulonglong2*)&AS[kk * LDT + ty * 4];       \
        ulonglong2 a23 = *(const ulonglong2*)&AS[kk * LDT + 64 + ty * 4];  \
        float4 b0 = *(const float4*)&BS[kk * LDT + tx * 4];                \
        float4 b1 = *(const float4*)&BS[kk * LDT + 64 + tx * 4];           \
        unsigned long long bp[8];                                          \
        bp[0] = pk2(b0.x); bp[1] = pk2(b0.y); bp[2] = pk2(b0.z); bp[3] = pk2(b0.w); \
        bp[4] = pk2(b1.x); bp[5] = pk2(b1.y); bp[6] = pk2(b1.z); bp[7] = pk2(b1.w); \
        _Pragma("unroll")                                        \
        for (int j = 0; j < 8; j++) {                            \
            fma2(acc[0][j], a01.x, bp[j]);                       \
            fma2(acc[1][j], a01.y, bp[j]);                       \
            fma2(acc[2][j], a23.x, bp[j]);                       \
            fma2(acc[3][j], a23.y, bp[j]);                       \
        }                                                        \
    }

__global__ __launch_bounds__(256, 2) void sgemm0_kernel(const float* __restrict__ x,
                                                        const float* __restrict__ Wa,
                                                        const float* __restrict__ Wk) {
    __shared__ __align__(16) float As0[16 * LDT];
    __shared__ __align__(16) float Bs0[16 * LDT];
    __shared__ __align__(16) float As1[16 * LDT];
    __shared__ __align__(16) float Bs1[16 * LDT];

    int bm = blockIdx.x * 128;
    int bn_c = blockIdx.y * 128;
    int kbeg = blockIdx.z * (DM / SK0);
    float* C = g_Hp + (size_t)blockIdx.z * TOKENS * NH;

    int tid = threadIdx.x;
    int am = tid >> 1, ak = (tid & 1) << 3;
    int bkr = tid >> 4, bn0 = (tid & 15) << 3;
    int ty = tid >> 4, tx = tid & 15;

    const float* Ap = x + (size_t)(bm + am) * DM + kbeg + ak;
    const float* Bp; int ldb;
    if (blockIdx.y < 3) { Bp = Wa + (size_t)(kbeg + bkr) * 384 + bn_c + bn0; ldb = 384; }
    else                { Bp = Wk + (size_t)(kbeg + bkr) * 128 + bn0;        ldb = 128; }

    unsigned long long acc[4][8];
    #pragma unroll
    for (int i = 0; i < 4; i++)
        #pragma unroll
        for (int j = 0; j < 8; j++) acc[i][j] = 0ULL;

    float4 pa0, pa1, pb0, pb1;
    G0_LOAD(0);
    G0_STORE(As0, Bs0);
    __syncthreads();

    for (int kt = 0; kt < DM / SK0; kt += 32) {
        G0_LOAD(kt + 16);
        G0_COMPUTE(As0, Bs0);
        G0_STORE(As1, Bs1);
        __syncthreads();

        if (kt + 32 < DM / SK0) { G0_LOAD(kt + 32); }
        G0_COMPUTE(As1, Bs1);
        if (kt + 32 < DM / SK0) { G0_STORE(As0, Bs0); }
        __syncthreads();
    }

    #pragma unroll
    for (int mi = 0; mi < 4; mi++) {
        int row = bm + ((mi < 2) ? (ty * 4 + mi * 2) : (64 + ty * 4 + (mi - 2) * 2));
        #pragma unroll
        for (int j = 0; j < 8; j++) {
            int col = bn_c + ((j < 4) ? (tx * 4 + j) : (64 + tx * 4 + (j - 4)));
            float2 v = upk(acc[mi][j]);
            C[(size_t)row * NH + col] = v.x;
            C[(size_t)(row + 1) * NH + col] = v.y;
        }
    }
}

// ---------------- reduce split-K partials for H (adds bias) ----------------
__global__ void reduceH_kernel() {
    int i = blockIdx.x * blockDim.x + threadIdx.x;
    const float4* p = (const float4*)g_Hp;
    constexpr int Q = TOKENS * NH / 4;
    float4 s = p[i];
    #pragma unroll
    for (int z = 1; z < SK0; z++) {
        float4 t = p[i + z * Q];
        s.x += t.x; s.y += t.y; s.z += t.z; s.w += t.w;
    }
    float4 b = ((const float4*)g_b)[i & 127];
    s.x += b.x; s.y += b.y; s.z += b.z; s.w += b.w;
    ((float4*)g_H)[i] = s;
}

// ---------------- block-diagonal cluster-score GEMM ----------------
__global__ void csgemm_kernel() {
    __shared__ __align__(16) float As[64 * 64];
    __shared__ __align__(16) float Bs[64 * 64];

    int byt = blockIdx.y;
    int kb0  = (byt == 0) ? 0 : (byt == 1) ? 128 : (byt == 2) ? 256 : 384;
    int cr0  = (byt < 2) ? 0 : (byt == 2) ? 64 : (byt == 3) ? 128 : 192;
    int base = byt * 64;
    int tok0 = blockIdx.x * 64;

    int t = threadIdx.x;
    int m = t & 63, c4 = t >> 6;
    int ty = t >> 4, tx = t & 15;

    unsigned long long acc[4][2];
    #pragma unroll
    for (int i = 0; i < 4; i++) { acc[i][0] = 0ULL; acc[i][1] = 0ULL; }

    const float* hrow = g_H + (size_t)(tok0 + m) * NH + kb0;
    const float* erow = g_ce + (size_t)(cr0 + m) * DS;

    for (int half = 0; half < 2; half++) {
        int kb = half * 64;
        #pragma unroll
        for (int i = 0; i < 4; i++) {
            int k0 = c4 * 4 + i * 16;
            float4 ve = *(const float4*)(erow + kb + k0);
            Bs[(k0 + 0) * 64 + m] = ve.x;
            Bs[(k0 + 1) * 64 + m] = ve.y;
            Bs[(k0 + 2) * 64 + m] = ve.z;
            Bs[(k0 + 3) * 64 + m] = ve.w;
            float4 vh = *(const float4*)(hrow + kb + k0);
            As[(k0 + 0) * 64 + m] = vh.x;
            As[(k0 + 1) * 64 + m] = vh.y;
            As[(k0 + 2) * 64 + m] = vh.z;
            As[(k0 + 3) * 64 + m] = vh.w;
        }
        __syncthreads();

        #pragma unroll 4
        for (int k = 0; k < 64; k++) {
            float a[4];
            *(float4*)a = *(const float4*)&As[k * 64 + ty * 4];
            ulonglong2 bb = *(const ulonglong2*)&Bs[k * 64 + tx * 4];
            #pragma unroll
            for (int i = 0; i < 4; i++) {
                unsigned long long ap = pk2(a[i]);
                fma2(acc[i][0], ap, bb.x);
                fma2(acc[i][1], ap, bb.y);
            }
        }
        __syncthreads();
    }

    #pragma unroll
    for (int i = 0; i < 4; i++) {
        int mm = ty * 4 + i;
        float2 p0 = upk(acc[i][0]);
        float2 p1 = upk(acc[i][1]);
        float4 v = make_float4(p0.x, p0.y, p1.x, p1.y);
        *(float4*)(g_csAll + (size_t)(tok0 + mm) * 320 + base + tx * 4) = v;
    }
}

// ---------------- cluster: softmax + top-8 + list build ----------------
__global__ void cluster_kernel() {
    int wid = threadIdx.x >> 5, lane = threadIdx.x & 31;
    int pair = blockIdx.x * 8 + wid;
    int token = pair >> 2, g = pair & 3;

    int nc   = (g == 3) ? 128 : 64;
    int base = (g < 3) ? g * 64 : 192;
    const float* cs = g_csAll + (size_t)token * 320 + base;

    float v[4];
    #pragma unroll
    for (int j = 0; j < 4; j++) {
        int c = j * 32 + lane;
        v[j] = (c < nc) ? cs[c] : -INFINITY;
    }

    float m = fmaxf(fmaxf(v[0], v[1]), fmaxf(v[2], v[3]));
    #pragma unroll
    for (int o = 16; o; o >>= 1) m = fmaxf(m, __shfl_xor_sync(0xffffffffu, m, o));
    float ssum = 0.f;
    #pragma unroll
    for (int j = 0; j < 4; j++) ssum += expf(v[j] - m);
    #pragma unroll
    for (int o = 16; o; o >>= 1) ssum += __shfl_xor_sync(0xffffffffu, ssum, o);

    #pragma unroll
    for (int j = 0; j < 4; j++) {
        int c = j * 32 + lane;
        if (c < nc) atomicAdd(&g_csum[base + c], expf(v[j] - m) / ssum);
    }

    unsigned rm = 0;
    int mytop = 0;
    for (int it = 0; it < 8; it++) {
        unsigned long long best = 0ULL;
        #pragma unroll
        for (int j = 0; j < 4; j++) {
            if (!((rm >> j) & 1u)) {
                int c = j * 32 + lane;
                unsigned b = __float_as_uint(v[j]);
                unsigned u = (b & 0x80000000u) ? ~b : (b | 0x80000000u);
                unsigned long long k = (((unsigned long long)u) << 32) | (unsigned)(256 - c);
                if (k > best) best = k;
            }
        }
        #pragma unroll
        for (int o = 16; o; o >>= 1) {
            unsigned long long t2 = __shfl_xor_sync(0xffffffffu, best, o);
            if (t2 > best) best = t2;
        }
        int idx = 256 - (int)(best & 0xffffffffu);
        if (it == lane) mytop = idx;
        if ((idx & 31) == lane) rm |= 1u << (idx >> 5);
    }

    if (lane < 8) {
        g_topc[(size_t)pair * 8 + lane] = mytop;
        int pos = atomicAdd(&g_cnt[base + mytop], 1);
        g_list[(size_t)(base + mytop) * 2048 + pos] = token | (lane << 16);
    }
}

// ---------------- cluster-grouped score GEMM (chunk-strided) ----------------
__global__ void score_kernel() {
    __shared__ __align__(16) float As[64 * 64];
    __shared__ __align__(16) float Bs[64 * 64];
    __shared__ int s_tok[64];
    __shared__ int s_slot[64];

    int gc = blockIdx.x;
    int cnt = g_cnt[gc];

    int g  = (gc < 64) ? 0 : (gc < 128) ? 1 : (gc < 192) ? 2 : 3;
    int cl = gc - ((g < 3) ? g * 64 : 192);
    int embbase = (g < 2) ? 0 : ((g == 2) ? 4096 : 8192);
    int nbase = embbase + cl * 64;

    int t = threadIdx.x;
    int m = t & 63, c4 = t >> 6;
    int ty = t >> 4, tx = t & 15;
    const float* erow = g_embn + (size_t)(nbase + m) * DS;

    for (int start = blockIdx.y * 64; start < cnt; start += 8 * 64) {
        __syncthreads();
        if (t < 64) {
            if (start + t < cnt) {
                int e = g_list[(size_t)gc * 2048 + start + t];
                s_tok[t] = e & 0xffff;
                s_slot[t] = e >> 16;
            } else {
                s_tok[t] = -1; s_slot[t] = 0;
            }
        }
        __syncthreads();

        unsigned long long acc[4][2];
        #pragma unroll
        for (int i = 0; i < 4; i++) { acc[i][0] = 0ULL; acc[i][1] = 0ULL; }

        int tok = s_tok[m];
        const float* hrow = (tok >= 0) ? (g_H + (size_t)tok * NH + g * 128) : g_embn;

        for (int half = 0; half < 2; half++) {
            int kb = half * 64;
            #pragma unroll
            for (int i = 0; i < 4; i++) {
                int k0 = c4 * 4 + i * 16;
                float4 ve = *(const float4*)(erow + kb + k0);
                Bs[(k0 + 0) * 64 + m] = ve.x;
                Bs[(k0 + 1) * 64 + m] = ve.y;
                Bs[(k0 + 2) * 64 + m] = ve.z;
                Bs[(k0 + 3) * 64 + m] = ve.w;
                float4 vh = *(const float4*)(hrow + kb + k0);
                As[(k0 + 0) * 64 + m] = vh.x;
                As[(k0 + 1) * 64 + m] = vh.y;
                As[(k0 + 2) * 64 + m] = vh.z;
                As[(k0 + 3) * 64 + m] = vh.w;
            }
            __syncthreads();

            #pragma unroll 4
            for (int k = 0; k < 64; k++) {
                float a[4];
                *(float4*)a = *(const float4*)&As[k * 64 + ty * 4];
                ulonglong2 bb = *(const ulonglong2*)&Bs[k * 64 + tx * 4];
                #pragma unroll
                for (int i = 0; i < 4; i++) {
                    unsigned long long ap = pk2(a[i]);
                    fma2(acc[i][0], ap, bb.x);
                    fma2(acc[i][1], ap, bb.y);
                }
            }
            __syncthreads();
        }

        #pragma unroll
        for (int i = 0; i < 4; i++) {
            int mm = ty * 4 + i;
            int tok2 = s_tok[mm];
            if (tok2 >= 0) {
                float2 p0 = upk(acc[i][0]);
                float2 p1 = upk(acc[i][1]);
                float4 v = make_float4(p0.x, p0.y, p1.x, p1.y);
                *(float4*)(g_scores + ((size_t)tok2 * 4 + g) * 512 + s_slot[mm] * 64 + tx * 4) = v;
            }
        }
    }
}

// ---------------- gate + FULL row write (block per token) ----------------
__global__ void gate_out_kernel(float* __restrict__ out) {
    int token = blockIdx.x;
    int tid = threadIdx.x, wid = tid >> 5, lane = tid & 31;

    __shared__ float s_val[4][512];
    __shared__ int   s_slot[4][128];

    s_slot[tid >> 7][tid & 127] = -1;
    s_slot[(tid + 256) >> 7][(tid + 256) & 127] = -1;
    __syncthreads();

    if (wid < 4) {
        int g = wid;
        int pair = token * 4 + g;
        int outbase = g * 4096;

        const float* srow = g_scores + (size_t)pair * 512;
        float tau = g_tau[pair];
        int tcl = (lane < 8) ? g_topc[(size_t)pair * 8 + lane] : 0;
        if (lane < 8) s_slot[g][tcl] = lane;

        float raw[16];
        unsigned u[16];
        unsigned lmax = 0;
        #pragma unroll
        for (int i = 0; i < 16; i++) {
            raw[i] = srow[i * 32 + lane] - tau;
            unsigned b = __float_as_uint(raw[i]);
            u[i] = (b & 0x80000000u) ? ~b : (b | 0x80000000u);
            lmax = (u[i] > lmax) ? u[i] : lmax;
        }
        unsigned umax = __reduce_max_sync(0xffffffffu, lmax);

        unsigned lo = 0, hi = umax;
        while (lo < hi) {
            unsigned mid = lo + ((hi - lo + 1) >> 1);
            int c = 0;
            #pragma unroll
            for (int i = 0; i < 16; i++) c += (u[i] >= mid);
            if (__reduce_add_sync(0xffffffffu, (unsigned)c) >= MAXK) lo = mid;
            else hi = mid - 1;
        }
        unsigned tb = (lo & 0x80000000u) ? (lo ^ 0x80000000u) : ~lo;
        unsigned mb = (umax & 0x80000000u) ? (umax ^ 0x80000000u) : ~umax;
        float raw_thr = __uint_as_float(tb);
        float eg_thr = fgate(raw_thr);
        float eg_max = fgate(__uint_as_float(mb));

        bool full = (eg_thr <= 4e-7f);
        float cand_lo = full ? -INFINITY : (raw_thr - 2.5e-7f);

        float eg[16];
        float s = 0.f;
        #pragma unroll
        for (int i = 0; i < 16; i++) {
            float e = -1.f;
            if (raw[i] >= cand_lo) {
                float ev = fgate(raw[i]);
                if (ev >= eg_thr) { e = ev; s += ev; }
            }
            eg[i] = e;
        }
        #pragma unroll
        for (int o = 16; o; o >>= 1) s += __shfl_xor_sync(0xffffffffu, s, o);
        float r = tanhf(eg_max) / (s + 1e-8f);

        #pragma unroll
        for (int i = 0; i < 16; i++) {
            int tc = __shfl_sync(0xffffffffu, tcl, i >> 1);   // convergent: all lanes
            float val = (eg[i] > 0.f) ? eg[i] * r : 0.f;
            s_val[g][i * 32 + lane] = val;
            if (val > 0.f) {
                int n = i * 32 + lane;
                atomicAdd(&g_nmass[outbase + tc * 64 + (n & 63)], val);
            }
        }
    }
    __syncthreads();

    float* orow = out + (size_t)token * OUTW;
    #pragma unroll
    for (int it = 0; it < 20; it++) {
        int idx = tid * 4 + it * 1024;
        int g = (idx < 12288) ? (idx >> 12) : 3;
        int local = idx - g * 4096;
        int cl = local >> 6;
        int s = s_slot[g][cl];
        float4 w = make_float4(0.f, 0.f, 0.f, 0.f);
        if (s >= 0) w = *(float4*)&s_val[g][s * 64 + (local & 63)];
        *(float4*)(orow + idx) = w;
    }
}

// ---------------- aux: parallel partial + write ----------------
__global__ void aux_partial_kernel() {
    int i = blockIdx.x * blockDim.x + threadIdx.x;
    int lane = threadIdx.x & 31, wid = threadIdx.x >> 5;
    double acc = 0.0;
    if (i < 320 + OUTW) {
        if (i < 320) {
            int nc = (i < 192) ? 64 : 128;
            double fr = (double)g_csum[i] / 2048.0;
            double d = fr - 1.0 / nc;
            acc = d * d * nc;
        } else {
            int j = i - 320;
            int N = (j < 12288) ? 4096 : 8192;
            double fr = (double)g_nmass[j] / 2048.0;
            double d = fr - 1.0 / N;
            acc = d * d * N;
        }
    }
    #pragma unroll
    for (int o = 16; o; o >>= 1) acc += __shfl_xor_sync(0xffffffffu, acc, o);
    __shared__ double rd[8];
    if (lane == 0) rd[wid] = acc;
    __syncthreads();
    if (threadIdx.x == 0) {
        double t = rd[0] + rd[1] + rd[2] + rd[3] + rd[4] + rd[5] + rd[6] + rd[7];
        atomicAdd(&g_aux, t);
    }
}

__global__ void aux_write_kernel(float* __restrict__ out, long long outsize) {
    out[outsize - 1] = (float)g_aux;
}

// ---------------- launch ----------------
extern "C" void kernel_launch(void* const* d_in, const int* in_sizes, int n_in,
                              void* d_out, int out_size) {
    const float* x    = (const float*)d_in[0];
    const float* emb  = (const float*)d_in[1];
    const float* Wa   = (const float*)d_in[2];
    const float* ba   = (const float*)d_in[3];
    const float* Wk   = (const float*)d_in[4];
    const float* bk   = (const float*)d_in[5];
    const float* Wta  = (const float*)d_in[6];
    const float* bta  = (const float*)d_in[7];
    const float* Wtk  = (const float*)d_in[8];
    const float* btk  = (const float*)d_in[9];
    const float* cqk  = (const float*)d_in[10];
    const float* cv   = (const float*)d_in[11];
    const float* cknw = (const float*)d_in[12];
    float* out = (float*)d_out;

    prep_kernel<<<NORM_BLOCKS + OUTW / 256, 256>>>(emb, cqk, cv, cknw, ba, bk);
    tau_kernel<<<TOKENS / 8, 256>>>(x, Wta, Wtk, bta, btk);
    sgemm0_kernel<<<dim3(16, 4, SK0), 256>>>(x, Wa, Wk);
    reduceH_kernel<<<TOKENS * NH / 4 / 256, 256>>>();
    csgemm_kernel<<<dim3(32, 5), 256>>>();
    cluster_kernel<<<TOKENS * 4 / 8, 256>>>();
    score_kernel<<<dim3(320, 8), 256>>>();
    gate_out_kernel<<<TOKENS, 256>>>(out);
    aux_partial_kernel<<<(320 + OUTW + 255) / 256, 256>>>();
    aux_write_kernel<<<1, 1>>>(out, (long long)out_size);
}

// round 17
// speedup vs baseline: 1.2049x; 1.0001x over previous
#include <cuda_runtime.h>
#include <math.h>
#include <stdint.h>

// ---------------- problem constants ----------------
#define TOKENS 2048
#define DM     2048
#define DS     128
#define NH     512
#define NTOT   16384
#define NCET   256
#define OUTW   20480
#define MAXK   32
#define SK0    4

// ---------------- device scratch ----------------
__device__ float  g_H[TOKENS * NH];
__device__ float  g_Hp[SK0 * TOKENS * NH];
__device__ float  g_b[NH];
__device__ float  g_tau[TOKENS * 4];
__device__ float  g_embn[NTOT * DS];
__device__ float  g_ce[NCET * DS];
__device__ float  g_csAll[TOKENS * 320];
__device__ float  g_csum[320];
__device__ float  g_nmass[OUTW];
__device__ int    g_cnt[320];
__device__ int    g_list[320 * 2048];
__device__ int    g_topc[TOKENS * 4 * 8];
__device__ float  g_scores[TOKENS * 4 * 512];
__device__ double g_aux;

// ---------------- f32x2 packed helpers ----------------
__device__ __forceinline__ unsigned long long pk2(float x) {
    unsigned long long r;
    asm("mov.b64 %0, {%1, %1};" : "=l"(r) : "f"(x));
    return r;
}
__device__ __forceinline__ void fma2(unsigned long long& c,
                                     unsigned long long a, unsigned long long b) {
    asm("fma.rn.f32x2 %0, %1, %2, %0;" : "+l"(c) : "l"(a), "l"(b));
}
__device__ __forceinline__ float2 upk(unsigned long long p) {
    float2 f;
    asm("mov.b64 {%0, %1}, %2;" : "=f"(f.x), "=f"(f.y) : "l"(p));
    return f;
}

// gate nonlinearity (matches reference float path)
__device__ __forceinline__ float fgate(float raw) {
    float gt = (raw > 0.f) ? raw : 1e-8f * expf(raw);
    return expf(gt) - 1.0f;
}

// ---------------- prep: emb norm + init + tau (fused, branch on blockIdx) ---
#define NORM_BLOCKS ((NTOT + NCET) / 8)     // 2080
#define INIT_BLOCKS (OUTW / 256)            // 80
__global__ void prep_kernel(const float* __restrict__ emb,
                            const float* __restrict__ cqk,
                            const float* __restrict__ cv,
                            const float* __restrict__ cknow,
                            const float* __restrict__ ba, const float* __restrict__ bk,
                            const float* __restrict__ x,
                            const float* __restrict__ Wta, const float* __restrict__ Wtk,
                            const float* __restrict__ bta, const float* __restrict__ btk) {
    if (blockIdx.x < NORM_BLOCKS) {
        int wid = threadIdx.x >> 5, lane = threadIdx.x & 31;
        int r = blockIdx.x * 8 + wid;
        const float* src;
        if (r < NTOT) {
            src = emb + (size_t)r * DS;
        } else {
            int c = r - NTOT;
            if (c < 64)       src = cqk + (size_t)c * DS;
            else if (c < 128) src = cv + (size_t)(c - 64) * DS;
            else              src = cknow + (size_t)(c - 128) * DS;
        }
        float4 v = ((const float4*)src)[lane];
        float ss = v.x * v.x + v.y * v.y + v.z * v.z + v.w * v.w;
        #pragma unroll
        for (int o = 16; o; o >>= 1) ss += __shfl_xor_sync(0xffffffffu, ss, o);
        float invn = 1.0f / (sqrtf(ss) + 1e-8f);
        float4 ov = make_float4(v.x * invn, v.y * invn, v.z * invn, v.w * invn);
        if (r < NTOT) ((float4*)(g_embn + (size_t)r * DS))[lane] = ov;
        else          ((float4*)(g_ce + (size_t)(r - NTOT) * DS))[lane] = ov;
    } else if (blockIdx.x < NORM_BLOCKS + INIT_BLOCKS) {
        int i = (blockIdx.x - NORM_BLOCKS) * 256 + threadIdx.x;   // 0..20479
        if (i < 320) { g_csum[i] = 0.f; g_cnt[i] = 0; }
        if (i < OUTW) g_nmass[i] = 0.f;
        if (i < NH) g_b[i] = (i < 384) ? ba[i] : bk[i - 384];
        if (i == 0) g_aux = 0.0;
    } else {
        // tau: warp per token
        int wid = threadIdx.x >> 5, lane = threadIdx.x & 31;
        int token = (blockIdx.x - NORM_BLOCKS - INIT_BLOCKS) * 8 + wid;
        const float* xr = x + (size_t)token * DM;
        float a0 = 0.f, a1 = 0.f, a2 = 0.f, a3 = 0.f;
        #pragma unroll
        for (int q = 0; q < 16; q++) {
            int k0 = q * 128 + lane * 4;
            float4 xv = *(const float4*)(xr + k0);
            const float4* wp = (const float4*)(Wta + (size_t)3 * k0);
            float4 t0 = wp[0], t1 = wp[1], t2 = wp[2];
            float4 wk = *(const float4*)(Wtk + k0);
            a0 = fmaf(xv.x, t0.x, fmaf(xv.y, t0.w, fmaf(xv.z, t1.z, fmaf(xv.w, t2.y, a0))));
            a1 = fmaf(xv.x, t0.y, fmaf(xv.y, t1.x, fmaf(xv.z, t1.w, fmaf(xv.w, t2.z, a1))));
            a2 = fmaf(xv.x, t0.z, fmaf(xv.y, t1.y, fmaf(xv.z, t2.x, fmaf(xv.w, t2.w, a2))));
            a3 = fmaf(xv.x, wk.x, fmaf(xv.y, wk.y, fmaf(xv.z, wk.z, fmaf(xv.w, wk.w, a3))));
        }
        #pragma unroll
        for (int o = 16; o; o >>= 1) {
            a0 += __shfl_xor_sync(0xffffffffu, a0, o);
            a1 += __shfl_xor_sync(0xffffffffu, a1, o);
            a2 += __shfl_xor_sync(0xffffffffu, a2, o);
            a3 += __shfl_xor_sync(0xffffffffu, a3, o);
        }
        if (lane == 0) {
            g_tau[token * 4 + 0] = a0 + bta[0];
            g_tau[token * 4 + 1] = a1 + bta[1];
            g_tau[token * 4 + 2] = a2 + bta[2];
            g_tau[token * 4 + 3] = a3 + btk[0];
        }
    }
}

// ---------------- GEMM0: double-buffered 8x8 FFMA2, direct Wa/Wk reads ------
#define LDT 132

#define G0_LOAD(KOFF)                                            \
    pa0 = *(const float4*)(Ap + (KOFF));                         \
    pa1 = *(const float4*)(Ap + (KOFF) + 4);                     \
    pb0 = *(const float4*)(Bp + (size_t)(KOFF) * ldb);           \
    pb1 = *(const float4*)(Bp + (size_t)(KOFF) * ldb + 4);

#define G0_STORE(AS, BS)                                         \
    AS[(ak + 0) * LDT + am] = pa0.x;                             \
    AS[(ak + 1) * LDT + am] = pa0.y;                             \
    AS[(ak + 2) * LDT + am] = pa0.z;                             \
    AS[(ak + 3) * LDT + am] = pa0.w;                             \
    AS[(ak + 4) * LDT + am] = pa1.x;                             \
    AS[(ak + 5) * LDT + am] = pa1.y;                             \
    AS[(ak + 6) * LDT + am] = pa1.z;                             \
    AS[(ak + 7) * LDT + am] = pa1.w;                             \
    *(float4*)&BS[bkr * LDT + bn0] = pb0;                        \
    *(float4*)&BS[bkr * LDT + bn0 + 4] = pb1;

#define G0_COMPUTE(AS, BS)                                       \
    _Pragma("unroll")                                            \
    for (int kk = 0; kk < 16; kk++) {                            \
        ulonglong2 a01 = *(const ulonglong2*)&AS[kk * LDT + ty * 4];       \
        ulonglong2 a23 = *(const ulonglong2*)&AS[kk * LDT + 64 + ty * 4];  \
        float4 b0 = *(const float4*)&BS[kk * LDT + tx * 4];                \
        float4 b1 = *(const float4*)&BS[kk * LDT + 64 + tx * 4];           \
        unsigned long long bp[8];                                          \
        bp[0] = pk2(b0.x); bp[1] = pk2(b0.y); bp[2] = pk2(b0.z); bp[3] = pk2(b0.w); \
        bp[4] = pk2(b1.x); bp[5] = pk2(b1.y); bp[6] = pk2(b1.z); bp[7] = pk2(b1.w); \
        _Pragma("unroll")                                        \
        for (int j = 0; j < 8; j++) {                            \
            fma2(acc[0][j], a01.x, bp[j]);                       \
            fma2(acc[1][j], a01.y, bp[j]);                       \
            fma2(acc[2][j], a23.x, bp[j]);                       \
            fma2(acc[3][j], a23.y, bp[j]);                       \
        }                                                        \
    }

__global__ __launch_bounds__(256, 2) void sgemm0_kernel(const float* __restrict__ x,
                                                        const float* __restrict__ Wa,
                                                        const float* __restrict__ Wk) {
    __shared__ __align__(16) float As0[16 * LDT];
    __shared__ __align__(16) float Bs0[16 * LDT];
    __shared__ __align__(16) float As1[16 * LDT];
    __shared__ __align__(16) float Bs1[16 * LDT];

    int bm = blockIdx.x * 128;
    int bn_c = blockIdx.y * 128;
    int kbeg = blockIdx.z * (DM / SK0);
    float* C = g_Hp + (size_t)blockIdx.z * TOKENS * NH;

    int tid = threadIdx.x;
    int am = tid >> 1, ak = (tid & 1) << 3;
    int bkr = tid >> 4, bn0 = (tid & 15) << 3;
    int ty = tid >> 4, tx = tid & 15;

    const float* Ap = x + (size_t)(bm + am) * DM + kbeg + ak;
    const float* Bp; int ldb;
    if (blockIdx.y < 3) { Bp = Wa + (size_t)(kbeg + bkr) * 384 + bn_c + bn0; ldb = 384; }
    else                { Bp = Wk + (size_t)(kbeg + bkr) * 128 + bn0;        ldb = 128; }

    unsigned long long acc[4][8];
    #pragma unroll
    for (int i = 0; i < 4; i++)
        #pragma unroll
        for (int j = 0; j < 8; j++) acc[i][j] = 0ULL;

    float4 pa0, pa1, pb0, pb1;
    G0_LOAD(0);
    G0_STORE(As0, Bs0);
    __syncthreads();

    for (int kt = 0; kt < DM / SK0; kt += 32) {
        G0_LOAD(kt + 16);
        G0_COMPUTE(As0, Bs0);
        G0_STORE(As1, Bs1);
        __syncthreads();

        if (kt + 32 < DM / SK0) { G0_LOAD(kt + 32); }
        G0_COMPUTE(As1, Bs1);
        if (kt + 32 < DM / SK0) { G0_STORE(As0, Bs0); }
        __syncthreads();
    }

    #pragma unroll
    for (int mi = 0; mi < 4; mi++) {
        int row = bm + ((mi < 2) ? (ty * 4 + mi * 2) : (64 + ty * 4 + (mi - 2) * 2));
        #pragma unroll
        for (int j = 0; j < 8; j++) {
            int col = bn_c + ((j < 4) ? (tx * 4 + j) : (64 + tx * 4 + (j - 4)));
            float2 v = upk(acc[mi][j]);
            C[(size_t)row * NH + col] = v.x;
            C[(size_t)(row + 1) * NH + col] = v.y;
        }
    }
}

// ---------------- reduce split-K partials (2 float4/thread, batched MLP) ----
__global__ void reduceH_kernel() {
    constexpr int Q = TOKENS * NH / 4;          // 262144 float4s
    constexpr int HALF = Q / 2;                 // 131072
    int i = blockIdx.x * blockDim.x + threadIdx.x;
    const float4* p = (const float4*)g_Hp;

    float4 a[SK0], b[SK0];
    #pragma unroll
    for (int z = 0; z < SK0; z++) {
        a[z] = p[i + z * Q];
        b[z] = p[i + HALF + z * Q];
    }
    float4 s0 = a[0], s1 = b[0];
    #pragma unroll
    for (int z = 1; z < SK0; z++) {
        s0.x += a[z].x; s0.y += a[z].y; s0.z += a[z].z; s0.w += a[z].w;
        s1.x += b[z].x; s1.y += b[z].y; s1.z += b[z].z; s1.w += b[z].w;
    }
    float4 b0 = ((const float4*)g_b)[i & 127];
    float4 b1 = ((const float4*)g_b)[(i + HALF) & 127];
    s0.x += b0.x; s0.y += b0.y; s0.z += b0.z; s0.w += b0.w;
    s1.x += b1.x; s1.y += b1.y; s1.z += b1.z; s1.w += b1.w;
    ((float4*)g_H)[i] = s0;
    ((float4*)g_H)[i + HALF] = s1;
}

// ---------------- block-diagonal cluster-score GEMM ----------------
__global__ void csgemm_kernel() {
    __shared__ __align__(16) float As[64 * 64];
    __shared__ __align__(16) float Bs[64 * 64];

    int byt = blockIdx.y;
    int kb0  = (byt == 0) ? 0 : (byt == 1) ? 128 : (byt == 2) ? 256 : 384;
    int cr0  = (byt < 2) ? 0 : (byt == 2) ? 64 : (byt == 3) ? 128 : 192;
    int base = byt * 64;
    int tok0 = blockIdx.x * 64;

    int t = threadIdx.x;
    int m = t & 63, c4 = t >> 6;
    int ty = t >> 4, tx = t & 15;

    unsigned long long acc[4][2];
    #pragma unroll
    for (int i = 0; i < 4; i++) { acc[i][0] = 0ULL; acc[i][1] = 0ULL; }

    const float* hrow = g_H + (size_t)(tok0 + m) * NH + kb0;
    const float* erow = g_ce + (size_t)(cr0 + m) * DS;

    for (int half = 0; half < 2; half++) {
        int kb = half * 64;
        #pragma unroll
        for (int i = 0; i < 4; i++) {
            int k0 = c4 * 4 + i * 16;
            float4 ve = *(const float4*)(erow + kb + k0);
            Bs[(k0 + 0) * 64 + m] = ve.x;
            Bs[(k0 + 1) * 64 + m] = ve.y;
            Bs[(k0 + 2) * 64 + m] = ve.z;
            Bs[(k0 + 3) * 64 + m] = ve.w;
            float4 vh = *(const float4*)(hrow + kb + k0);
            As[(k0 + 0) * 64 + m] = vh.x;
            As[(k0 + 1) * 64 + m] = vh.y;
            As[(k0 + 2) * 64 + m] = vh.z;
            As[(k0 + 3) * 64 + m] = vh.w;
        }
        __syncthreads();

        #pragma unroll 4
        for (int k = 0; k < 64; k++) {
            float a[4];
            *(float4*)a = *(const float4*)&As[k * 64 + ty * 4];
            ulonglong2 bb = *(const ulonglong2*)&Bs[k * 64 + tx * 4];
            #pragma unroll
            for (int i = 0; i < 4; i++) {
                unsigned long long ap = pk2(a[i]);
                fma2(acc[i][0], ap, bb.x);
                fma2(acc[i][1], ap, bb.y);
            }
        }
        __syncthreads();
    }

    #pragma unroll
    for (int i = 0; i < 4; i++) {
        int mm = ty * 4 + i;
        float2 p0 = upk(acc[i][0]);
        float2 p1 = upk(acc[i][1]);
        float4 v = make_float4(p0.x, p0.y, p1.x, p1.y);
        *(float4*)(g_csAll + (size_t)(tok0 + mm) * 320 + base + tx * 4) = v;
    }
}

// ---------------- cluster: softmax + top-8 + list build ----------------
__global__ void cluster_kernel() {
    int wid = threadIdx.x >> 5, lane = threadIdx.x & 31;
    int pair = blockIdx.x * 8 + wid;
    int token = pair >> 2, g = pair & 3;

    int nc   = (g == 3) ? 128 : 64;
    int base = (g < 3) ? g * 64 : 192;
    const float* cs = g_csAll + (size_t)token * 320 + base;

    float v[4];
    #pragma unroll
    for (int j = 0; j < 4; j++) {
        int c = j * 32 + lane;
        v[j] = (c < nc) ? cs[c] : -INFINITY;
    }

    float m = fmaxf(fmaxf(v[0], v[1]), fmaxf(v[2], v[3]));
    #pragma unroll
    for (int o = 16; o; o >>= 1) m = fmaxf(m, __shfl_xor_sync(0xffffffffu, m, o));
    float ssum = 0.f;
    #pragma unroll
    for (int j = 0; j < 4; j++) ssum += expf(v[j] - m);
    #pragma unroll
    for (int o = 16; o; o >>= 1) ssum += __shfl_xor_sync(0xffffffffu, ssum, o);

    #pragma unroll
    for (int j = 0; j < 4; j++) {
        int c = j * 32 + lane;
        if (c < nc) atomicAdd(&g_csum[base + c], expf(v[j] - m) / ssum);
    }

    unsigned rm = 0;
    int mytop = 0;
    for (int it = 0; it < 8; it++) {
        unsigned long long best = 0ULL;
        #pragma unroll
        for (int j = 0; j < 4; j++) {
            if (!((rm >> j) & 1u)) {
                int c = j * 32 + lane;
                unsigned b = __float_as_uint(v[j]);
                unsigned u = (b & 0x80000000u) ? ~b : (b | 0x80000000u);
                unsigned long long k = (((unsigned long long)u) << 32) | (unsigned)(256 - c);
                if (k > best) best = k;
            }
        }
        #pragma unroll
        for (int o = 16; o; o >>= 1) {
            unsigned long long t2 = __shfl_xor_sync(0xffffffffu, best, o);
            if (t2 > best) best = t2;
        }
        int idx = 256 - (int)(best & 0xffffffffu);
        if (it == lane) mytop = idx;
        if ((idx & 31) == lane) rm |= 1u << (idx >> 5);
    }

    if (lane < 8) {
        g_topc[(size_t)pair * 8 + lane] = mytop;
        int pos = atomicAdd(&g_cnt[base + mytop], 1);
        g_list[(size_t)(base + mytop) * 2048 + pos] = token | (lane << 16);
    }
}

// ---------------- score GEMM: persistent neuron tile + chunk loop -----------
// dynamic smem: Bs [128][64] persistent (32KB) + As [64][64] (16KB) = 48KB
__global__ void score_kernel() {
    extern __shared__ __align__(16) float sm[];
    float* Bs = sm;               // [k 0..127][n 0..63]
    float* As = sm + 128 * 64;    // [k 0..63][m 0..63] per half
    __shared__ int s_tok[64];
    __shared__ int s_slot[64];

    int gc = blockIdx.x;
    int cnt = g_cnt[gc];
    if ((int)blockIdx.y * 64 >= cnt) return;

    int g  = (gc < 64) ? 0 : (gc < 128) ? 1 : (gc < 192) ? 2 : 3;
    int cl = gc - ((g < 3) ? g * 64 : 192);
    int embbase = (g < 2) ? 0 : ((g == 2) ? 4096 : 8192);
    int nbase = embbase + cl * 64;

    int t = threadIdx.x;
    int m = t & 63, c4 = t >> 6;
    int ty = t >> 4, tx = t & 15;

    // load the full neuron tile once (both K-halves)
    {
        const float* erow = g_embn + (size_t)(nbase + m) * DS;
        #pragma unroll
        for (int i = 0; i < 8; i++) {
            int k0 = c4 * 4 + i * 16;
            float4 ve = *(const float4*)(erow + k0);
            Bs[(k0 + 0) * 64 + m] = ve.x;
            Bs[(k0 + 1) * 64 + m] = ve.y;
            Bs[(k0 + 2) * 64 + m] = ve.z;
            Bs[(k0 + 3) * 64 + m] = ve.w;
        }
    }

    for (int start = blockIdx.y * 64; start < cnt; start += 8 * 64) {
        __syncthreads();
        if (t < 64) {
            if (start + t < cnt) {
                int e = g_list[(size_t)gc * 2048 + start + t];
                s_tok[t] = e & 0xffff;
                s_slot[t] = e >> 16;
            } else {
                s_tok[t] = -1; s_slot[t] = 0;
            }
        }
        __syncthreads();

        unsigned long long acc[4][2];
        #pragma unroll
        for (int i = 0; i < 4; i++) { acc[i][0] = 0ULL; acc[i][1] = 0ULL; }

        int tok = s_tok[m];
        const float* hrow = (tok >= 0) ? (g_H + (size_t)tok * NH + g * 128) : g_embn;

        for (int half = 0; half < 2; half++) {
            int kb = half * 64;
            #pragma unroll
            for (int i = 0; i < 4; i++) {
                int k0 = c4 * 4 + i * 16;
                float4 vh = *(const float4*)(hrow + kb + k0);
                As[(k0 + 0) * 64 + m] = vh.x;
                As[(k0 + 1) * 64 + m] = vh.y;
                As[(k0 + 2) * 64 + m] = vh.z;
                As[(k0 + 3) * 64 + m] = vh.w;
            }
            __syncthreads();

            #pragma unroll 4
            for (int k = 0; k < 64; k++) {
                float a[4];
                *(float4*)a = *(const float4*)&As[k * 64 + ty * 4];
                ulonglong2 bb = *(const ulonglong2*)&Bs[(kb + k) * 64 + tx * 4];
                #pragma unroll
                for (int i = 0; i < 4; i++) {
                    unsigned long long ap = pk2(a[i]);
                    fma2(acc[i][0], ap, bb.x);
                    fma2(acc[i][1], ap, bb.y);
                }
            }
            __syncthreads();
        }

        #pragma unroll
        for (int i = 0; i < 4; i++) {
            int mm = ty * 4 + i;
            int tok2 = s_tok[mm];
            if (tok2 >= 0) {
                float2 p0 = upk(acc[i][0]);
                float2 p1 = upk(acc[i][1]);
                float4 v = make_float4(p0.x, p0.y, p1.x, p1.y);
                *(float4*)(g_scores + ((size_t)tok2 * 4 + g) * 512 + s_slot[mm] * 64 + tx * 4) = v;
            }
        }
    }
}

// ---------------- gate + FULL row write (block per token) ----------------
__global__ void gate_out_kernel(float* __restrict__ out) {
    int token = blockIdx.x;
    int tid = threadIdx.x, wid = tid >> 5, lane = tid & 31;

    __shared__ float s_val[4][512];
    __shared__ int   s_slot[4][128];

    s_slot[tid >> 7][tid & 127] = -1;
    s_slot[(tid + 256) >> 7][(tid + 256) & 127] = -1;
    __syncthreads();

    if (wid < 4) {
        int g = wid;
        int pair = token * 4 + g;
        int outbase = g * 4096;

        const float* srow = g_scores + (size_t)pair * 512;
        float tau = g_tau[pair];
        int tcl = (lane < 8) ? g_topc[(size_t)pair * 8 + lane] : 0;
        if (lane < 8) s_slot[g][tcl] = lane;

        float raw[16];
        unsigned u[16];
        unsigned lmax = 0;
        #pragma unroll
        for (int i = 0; i < 16; i++) {
            raw[i] = srow[i * 32 + lane] - tau;
            unsigned b = __float_as_uint(raw[i]);
            u[i] = (b & 0x80000000u) ? ~b : (b | 0x80000000u);
            lmax = (u[i] > lmax) ? u[i] : lmax;
        }
        unsigned umax = __reduce_max_sync(0xffffffffu, lmax);

        unsigned lo = 0, hi = umax;
        while (lo < hi) {
            unsigned mid = lo + ((hi - lo + 1) >> 1);
            int c = 0;
            #pragma unroll
            for (int i = 0; i < 16; i++) c += (u[i] >= mid);
            if (__reduce_add_sync(0xffffffffu, (unsigned)c) >= MAXK) lo = mid;
            else hi = mid - 1;
        }
        unsigned tb = (lo & 0x80000000u) ? (lo ^ 0x80000000u) : ~lo;
        unsigned mb = (umax & 0x80000000u) ? (umax ^ 0x80000000u) : ~umax;
        float raw_thr = __uint_as_float(tb);
        float eg_thr = fgate(raw_thr);
        float eg_max = fgate(__uint_as_float(mb));

        bool full = (eg_thr <= 4e-7f);
        float cand_lo = full ? -INFINITY : (raw_thr - 2.5e-7f);

        float eg[16];
        float s = 0.f;
        #pragma unroll
        for (int i = 0; i < 16; i++) {
            float e = -1.f;
            if (raw[i] >= cand_lo) {
                float ev = fgate(raw[i]);
                if (ev >= eg_thr) { e = ev; s += ev; }
            }
            eg[i] = e;
        }
        #pragma unroll
        for (int o = 16; o; o >>= 1) s += __shfl_xor_sync(0xffffffffu, s, o);
        float r = tanhf(eg_max) / (s + 1e-8f);

        #pragma unroll
        for (int i = 0; i < 16; i++) {
            int tc = __shfl_sync(0xffffffffu, tcl, i >> 1);   // convergent
            float val = (eg[i] > 0.f) ? eg[i] * r : 0.f;
            s_val[g][i * 32 + lane] = val;
            if (val > 0.f) {
                int n = i * 32 + lane;
                atomicAdd(&g_nmass[outbase + tc * 64 + (n & 63)], val);
            }
        }
    }
    __syncthreads();

    float* orow = out + (size_t)token * OUTW;
    #pragma unroll
    for (int it = 0; it < 20; it++) {
        int idx = tid * 4 + it * 1024;
        int g = (idx < 12288) ? (idx >> 12) : 3;
        int local = idx - g * 4096;
        int cl = local >> 6;
        int s = s_slot[g][cl];
        float4 w = make_float4(0.f, 0.f, 0.f, 0.f);
        if (s >= 0) w = *(float4*)&s_val[g][s * 64 + (local & 63)];
        __stcs((float4*)(orow + idx), w);
    }
}

// ---------------- aux: parallel partial + write ----------------
__global__ void aux_partial_kernel() {
    int i = blockIdx.x * blockDim.x + threadIdx.x;
    int lane = threadIdx.x & 31, wid = threadIdx.x >> 5;
    double acc = 0.0;
    if (i < 320 + OUTW) {
        if (i < 320) {
            int nc = (i < 192) ? 64 : 128;
            double fr = (double)g_csum[i] / 2048.0;
            double d = fr - 1.0 / nc;
            acc = d * d * nc;
        } else {
            int j = i - 320;
            int N = (j < 12288) ? 4096 : 8192;
            double fr = (double)g_nmass[j] / 2048.0;
            double d = fr - 1.0 / N;
            acc = d * d * N;
        }
    }
    #pragma unroll
    for (int o = 16; o; o >>= 1) acc += __shfl_xor_sync(0xffffffffu, acc, o);
    __shared__ double rd[8];
    if (lane == 0) rd[wid] = acc;
    __syncthreads();
    if (threadIdx.x == 0) {
        double t = rd[0] + rd[1] + rd[2] + rd[3] + rd[4] + rd[5] + rd[6] + rd[7];
        atomicAdd(&g_aux, t);
    }
}

__global__ void aux_write_kernel(float* __restrict__ out, long long outsize) {
    out[outsize - 1] = (float)g_aux;
}

// ---------------- launch ----------------
extern "C" void kernel_launch(void* const* d_in, const int* in_sizes, int n_in,
                              void* d_out, int out_size) {
    const float* x    = (const float*)d_in[0];
    const float* emb  = (const float*)d_in[1];
    const float* Wa   = (const float*)d_in[2];
    const float* ba   = (const float*)d_in[3];
    const float* Wk   = (const float*)d_in[4];
    const float* bk   = (const float*)d_in[5];
    const float* Wta  = (const float*)d_in[6];
    const float* bta  = (const float*)d_in[7];
    const float* Wtk  = (const float*)d_in[8];
    const float* btk  = (const float*)d_in[9];
    const float* cqk  = (const float*)d_in[10];
    const float* cv   = (const float*)d_in[11];
    const float* cknw = (const float*)d_in[12];
    float* out = (float*)d_out;

    const int SCORE_SMEM = (128 * 64 + 64 * 64) * 4;   // 49152 B
    cudaFuncSetAttribute(score_kernel,
                         cudaFuncAttributeMaxDynamicSharedMemorySize, SCORE_SMEM);

    prep_kernel<<<NORM_BLOCKS + INIT_BLOCKS + TOKENS / 8, 256>>>(
        emb, cqk, cv, cknw, ba, bk, x, Wta, Wtk, bta, btk);
    sgemm0_kernel<<<dim3(16, 4, SK0), 256>>>(x, Wa, Wk);
    reduceH_kernel<<<TOKENS * NH / 8 / 256, 256>>>();
    csgemm_kernel<<<dim3(32, 5), 256>>>();
    cluster_kernel<<<TOKENS * 4 / 8, 256>>>();
    score_kernel<<<dim3(320, 8), 256, SCORE_SMEM>>>();
    gate_out_kernel<<<TOKENS, 256>>>(out);
    aux_partial_kernel<<<(320 + OUTW + 255) / 256, 256>>>();
    aux_write_kernel<<<1, 1>>>(out, (long long)out_size);
}